// round 1
// baseline (speedup 1.0000x reference)
#include <cuda_runtime.h>
#include <cstdint>

// ---------------------------------------------------------------------------
// FragmentGraphEncoder: GNN forward
//   h = x@W_in + b_in
//   3x: agg = segment_sum(h[src], dst); h = relu(LN(h@W_root + agg@W_neigh + b))
//   out = (segment_mean(h, batch)) @ W_out + b_out
// ---------------------------------------------------------------------------

#define H 512
#define INF 16
#define LAYERS 3
#define NMAX 50176          // capacity for node scratch (N = 50000)
#define GMAX 512

// scratch (static device globals: allocation-free)
__device__ float g_hA[(size_t)NMAX * H];
__device__ float g_hB[(size_t)NMAX * H];
__device__ float g_agg[(size_t)NMAX * H];
__device__ float g_pooled[GMAX * H];
__device__ float g_counts[GMAX];
__device__ int   g_flags[2];   // [0]: edge_index is int64, [1]: batch is int64

// ---------------------------------------------------------------------------
__device__ __forceinline__ void red_add_v4(float* addr, float4 v) {
    asm volatile("red.global.add.v4.f32 [%0], {%1, %2, %3, %4};"
                 :: "l"(addr), "f"(v.x), "f"(v.y), "f"(v.z), "f"(v.w)
                 : "memory");
}

// Detect int64 vs int32 index buffers: viewed as int32 words, an int64 buffer
// of small non-negative values has every odd word == 0. n_words = element
// count (safe lower bound on buffer size in words for both dtypes).
__global__ void detect_i64(const int* __restrict__ w, long n_words, int* flag) {
    long i = (long)blockIdx.x * blockDim.x + threadIdx.x;
    long idx = 2 * i + 1;
    if (idx < n_words && w[idx] != 0) *flag = 0;
}

__device__ __forceinline__ long ld_idx(const void* p, long i, int f64) {
    return f64 ? (long)((const long long*)p)[i] : (long)((const int*)p)[i];
}

// ---------------------------------------------------------------------------
// h0 = x @ W_in + b_in.   256 threads, 16 nodes/block, 2 cols/thread.
__global__ void in_gemm(const float* __restrict__ x, const float* __restrict__ Win,
                        const float* __restrict__ bin, float* __restrict__ h, int N) {
    __shared__ float xs[16][17];
    int nb = blockIdx.x * 16;
    int tid = threadIdx.x;
    {
        int n = tid >> 4, k = tid & 15;
        int gn = nb + n;
        xs[n][k] = (gn < N) ? x[(size_t)gn * INF + k] : 0.f;
    }
    __syncthreads();
    float w0[16], w1[16];
#pragma unroll
    for (int k = 0; k < 16; k++) {
        w0[k] = Win[k * H + tid];
        w1[k] = Win[k * H + tid + 256];
    }
    float b0 = bin[tid], b1 = bin[tid + 256];
    for (int n = 0; n < 16; n++) {
        int gn = nb + n;
        if (gn >= N) break;
        float a0 = b0, a1 = b1;
#pragma unroll
        for (int k = 0; k < 16; k++) {
            float xv = xs[n][k];
            a0 += xv * w0[k];
            a1 += xv * w1[k];
        }
        h[(size_t)gn * H + tid]       = a0;
        h[(size_t)gn * H + tid + 256] = a1;
    }
}

// ---------------------------------------------------------------------------
// agg[dst] += h[src] over all edges. 128 threads per edge, vector reductions.
__global__ void scatter(const float* __restrict__ h,
                        const void* __restrict__ ei, int E, const int* __restrict__ flag) {
    int f64 = flag[0];
    int esub = threadIdx.x >> 7;
    int lane = threadIdx.x & 127;
    long e = (long)blockIdx.x * 2 + esub;
    if (e >= E) return;
    long src = ld_idx(ei, e, f64);
    long dst = ld_idx(ei, (long)E + e, f64);
    float4 v = ((const float4*)(h + src * H))[lane];
    red_add_v4(g_agg + dst * H + 4 * lane, v);
}

// ---------------------------------------------------------------------------
// C = A1@W1 + A2@W2 + bias.  128x128 tile, BK=16, 8x8 register tile.
#define BM 128
#define BN 128
#define BK 16

__global__ __launch_bounds__(256)
void conv_gemm(const float* __restrict__ A1, const float* __restrict__ A2,
               const float* __restrict__ W1, const float* __restrict__ W2,
               const float* __restrict__ bias, float* __restrict__ C, int M) {
    __shared__ float As[BK][BM + 4];
    __shared__ float Bs[BK][BN];
    int tid = threadIdx.x;
    int tx = tid & 15, ty = tid >> 4;
    int m0 = blockIdx.y * BM;
    int n0 = blockIdx.x * BN;
    float acc[8][8] = {};

    int ar = tid >> 2;        // A tile: rows ar, ar+64; cols ac..ac+3
    int ac = (tid & 3) * 4;
    int br = tid >> 5;        // B tile: rows br, br+8; cols bc..bc+3
    int bc = (tid & 31) * 4;

    for (int s = 0; s < 2; s++) {
        const float* A = s ? A2 : A1;
        const float* W = s ? W2 : W1;
        for (int kt = 0; kt < H; kt += BK) {
#pragma unroll
            for (int h2 = 0; h2 < 2; h2++) {
                int r = ar + 64 * h2;
                int gm = m0 + r;
                float4 v = make_float4(0.f, 0.f, 0.f, 0.f);
                if (gm < M) v = *(const float4*)(A + (size_t)gm * H + kt + ac);
                As[ac + 0][r] = v.x;
                As[ac + 1][r] = v.y;
                As[ac + 2][r] = v.z;
                As[ac + 3][r] = v.w;
            }
#pragma unroll
            for (int h2 = 0; h2 < 2; h2++) {
                int r = br + 8 * h2;
                *(float4*)&Bs[r][bc] =
                    *(const float4*)(W + (size_t)(kt + r) * H + n0 + bc);
            }
            __syncthreads();
#pragma unroll
            for (int k = 0; k < BK; k++) {
                float a[8], b[8];
                *(float4*)&a[0] = *(const float4*)&As[k][ty * 4];
                *(float4*)&a[4] = *(const float4*)&As[k][64 + ty * 4];
                *(float4*)&b[0] = *(const float4*)&Bs[k][tx * 4];
                *(float4*)&b[4] = *(const float4*)&Bs[k][64 + tx * 4];
#pragma unroll
                for (int i = 0; i < 8; i++)
#pragma unroll
                    for (int j = 0; j < 8; j++)
                        acc[i][j] += a[i] * b[j];
            }
            __syncthreads();
        }
    }
#pragma unroll
    for (int i = 0; i < 8; i++) {
        int r = (i < 4) ? (ty * 4 + i) : (64 + ty * 4 + (i - 4));
        int gm = m0 + r;
        if (gm >= M) continue;
#pragma unroll
        for (int jh = 0; jh < 2; jh++) {
            int c = jh ? (64 + tx * 4) : (tx * 4);
            float4 o;
            o.x = acc[i][jh * 4 + 0] + bias[n0 + c + 0];
            o.y = acc[i][jh * 4 + 1] + bias[n0 + c + 1];
            o.z = acc[i][jh * 4 + 2] + bias[n0 + c + 2];
            o.w = acc[i][jh * 4 + 3] + bias[n0 + c + 3];
            *(float4*)(C + (size_t)gm * H + n0 + c) = o;
        }
    }
}

// ---------------------------------------------------------------------------
// In-place LayerNorm + ReLU per row. 128 threads/row.
__global__ void ln_relu(float* __restrict__ h, const float* __restrict__ gamma,
                        const float* __restrict__ beta, int N) {
    long row = blockIdx.x;
    if (row >= N) return;
    int tid = threadIdx.x;
    float4 v = *(float4*)(h + row * H + tid * 4);
    float s  = v.x + v.y + v.z + v.w;
    float sq = v.x * v.x + v.y * v.y + v.z * v.z + v.w * v.w;
#pragma unroll
    for (int o = 16; o; o >>= 1) {
        s  += __shfl_xor_sync(~0u, s, o);
        sq += __shfl_xor_sync(~0u, sq, o);
    }
    __shared__ float ss[4], sqs[4];
    int w = tid >> 5;
    if ((tid & 31) == 0) { ss[w] = s; sqs[w] = sq; }
    __syncthreads();
    s  = ss[0] + ss[1] + ss[2] + ss[3];
    sq = sqs[0] + sqs[1] + sqs[2] + sqs[3];
    float mean = s * (1.f / H);
    float var  = sq * (1.f / H) - mean * mean;
    float rstd = rsqrtf(var + 1e-5f);
    int c = tid * 4;
    float4 g = *(const float4*)(gamma + c);
    float4 b = *(const float4*)(beta + c);
    v.x = fmaxf((v.x - mean) * rstd * g.x + b.x, 0.f);
    v.y = fmaxf((v.y - mean) * rstd * g.y + b.y, 0.f);
    v.z = fmaxf((v.z - mean) * rstd * g.z + b.z, 0.f);
    v.w = fmaxf((v.w - mean) * rstd * g.w + b.w, 0.f);
    *(float4*)(h + row * H + c) = v;
}

// ---------------------------------------------------------------------------
__global__ void pool(const float* __restrict__ h, const void* __restrict__ batch,
                     int N, const int* __restrict__ flag) {
    long n = blockIdx.x;
    if (n >= N) return;
    int f64 = flag[0];
    long g = ld_idx(batch, n, f64);
    int lane = threadIdx.x;
    float4 v = ((const float4*)(h + n * H))[lane];
    red_add_v4(g_pooled + g * H + 4 * lane, v);
    if (lane == 0) atomicAdd(&g_counts[g], 1.f);
}

// out[g] = (pooled[g]/cnt[g]) @ W_out + b_out.  128 threads, 4 cols/thread.
__global__ void out_gemm(const float* __restrict__ Wout, const float* __restrict__ bout,
                         float* __restrict__ out) {
    int g = blockIdx.x;
    __shared__ float ps[H];
    int tid = threadIdx.x;
    float inv = 1.f / fmaxf(g_counts[g], 1.f);
#pragma unroll
    for (int i = 0; i < 4; i++)
        ps[tid + i * 128] = g_pooled[(size_t)g * H + tid + i * 128] * inv;
    __syncthreads();
    float acc[4];
#pragma unroll
    for (int j = 0; j < 4; j++) acc[j] = bout[tid + j * 128];
    for (int k = 0; k < H; k++) {
        float p = ps[k];
#pragma unroll
        for (int j = 0; j < 4; j++)
            acc[j] += p * Wout[(size_t)k * H + tid + j * 128];
    }
#pragma unroll
    for (int j = 0; j < 4; j++) out[(size_t)g * H + tid + j * 128] = acc[j];
}

// ---------------------------------------------------------------------------
extern "C" void kernel_launch(void* const* d_in, const int* in_sizes, int n_in,
                              void* d_out, int out_size) {
    const float* x      = (const float*)d_in[0];
    const void*  ei     = d_in[1];
    const void*  batch  = d_in[2];
    const float* W_in   = (const float*)d_in[3];
    const float* b_in   = (const float*)d_in[4];
    const float* W_root = (const float*)d_in[5];
    const float* W_neigh= (const float*)d_in[6];
    const float* b_conv = (const float*)d_in[7];
    const float* ln_g   = (const float*)d_in[8];
    const float* ln_b   = (const float*)d_in[9];
    const float* W_out  = (const float*)d_in[10];
    const float* b_out  = (const float*)d_in[11];
    float* out = (float*)d_out;

    int N = in_sizes[0] / INF;
    int E = in_sizes[1] / 2;
    int G = out_size / H;

    void *pA, *pB, *pAgg, *pPool, *pCnt, *pFlags;
    cudaGetSymbolAddress(&pA, g_hA);
    cudaGetSymbolAddress(&pB, g_hB);
    cudaGetSymbolAddress(&pAgg, g_agg);
    cudaGetSymbolAddress(&pPool, g_pooled);
    cudaGetSymbolAddress(&pCnt, g_counts);
    cudaGetSymbolAddress(&pFlags, g_flags);
    float* hA = (float*)pA;
    float* hB = (float*)pB;
    int* flags = (int*)pFlags;

    // dtype sniffing for index tensors (int64 vs int32)
    cudaMemsetAsync(pFlags, 1, 2 * sizeof(int));
    {
        long nw = in_sizes[1];
        int blocks = (int)((nw / 2 + 255) / 256);
        detect_i64<<<blocks, 256>>>((const int*)ei, nw, flags + 0);
        nw = in_sizes[2];
        blocks = (int)((nw / 2 + 255) / 256);
        detect_i64<<<blocks, 256>>>((const int*)batch, nw, flags + 1);
    }

    in_gemm<<<(N + 15) / 16, 256>>>(x, W_in, b_in, hA, N);

    float* cur = hA;
    float* nxt = hB;
    for (int l = 0; l < LAYERS; l++) {
        cudaMemsetAsync(pAgg, 0, (size_t)N * H * sizeof(float));
        scatter<<<(E + 1) / 2, 256>>>(cur, ei, E, flags);
        dim3 grid(H / BN, (N + BM - 1) / BM);
        conv_gemm<<<grid, 256>>>(cur, (const float*)pAgg,
                                 W_root + (size_t)l * H * H,
                                 W_neigh + (size_t)l * H * H,
                                 b_conv + (size_t)l * H, nxt, N);
        ln_relu<<<N, 128>>>(nxt, ln_g + (size_t)l * H, ln_b + (size_t)l * H, N);
        float* t = cur; cur = nxt; nxt = t;
    }

    cudaMemsetAsync(pPool, 0, (size_t)G * H * sizeof(float));
    cudaMemsetAsync(pCnt, 0, G * sizeof(float));
    pool<<<N, 128>>>(cur, batch, N, flags + 1);
    out_gemm<<<G, 128>>>(W_out, b_out, out);
}

// round 4
// speedup vs baseline: 1.6594x; 1.6594x over previous
#include <cuda_runtime.h>
#include <cstdint>

// ---------------------------------------------------------------------------
// FragmentGraphEncoder: GNN forward, tf32 mma.sync conv GEMMs (base sm_100
// target: no tcgen05 available in this toolchain, legacy HMMA path instead)
// ---------------------------------------------------------------------------

#define H 512
#define INF 16
#define LAYERS 3
#define NMAX 50176
#define GMAX 512

__device__ float g_hA[(size_t)NMAX * H];
__device__ float g_hB[(size_t)NMAX * H];
__device__ float g_agg[(size_t)NMAX * H];
__device__ float g_Wt[(size_t)LAYERS * 2 * H * H];   // tf32-rounded, [n][k]
__device__ float g_pooled[GMAX * H];
__device__ float g_counts[GMAX];
__device__ int   g_flags[2];

// ---------------------------------------------------------------------------
__device__ __forceinline__ uint32_t cvt_tf32(float f) {
    uint32_t r; asm("cvt.rna.tf32.f32 %0, %1;" : "=r"(r) : "f"(f)); return r;
}
__device__ __forceinline__ void red_add_v4(float* addr, float4 v) {
    asm volatile("red.global.add.v4.f32 [%0], {%1, %2, %3, %4};"
                 :: "l"(addr), "f"(v.x), "f"(v.y), "f"(v.z), "f"(v.w) : "memory");
}
__device__ __forceinline__ void mma_tf32(float* c, const uint32_t* a, const uint32_t* b) {
    asm("mma.sync.aligned.m16n8k8.row.col.f32.tf32.tf32.f32 "
        "{%0,%1,%2,%3}, {%4,%5,%6,%7}, {%8,%9}, {%0,%1,%2,%3};"
        : "+f"(c[0]), "+f"(c[1]), "+f"(c[2]), "+f"(c[3])
        : "r"(a[0]), "r"(a[1]), "r"(a[2]), "r"(a[3]), "r"(b[0]), "r"(b[1]));
}

// Detect int64 vs int32 index buffers
__global__ void detect_i64(const int* __restrict__ w, long n_words, int* flag) {
    long i = (long)blockIdx.x * blockDim.x + threadIdx.x;
    long idx = 2 * i + 1;
    if (idx < n_words && w[idx] != 0) *flag = 0;
}
__device__ __forceinline__ long ld_idx(const void* p, long i, int f64) {
    return f64 ? (long)((const long long*)p)[i] : (long)((const int*)p)[i];
}

// ---------------------------------------------------------------------------
// g_Wt[mat][n][k] = rna_tf32(W[mat][k][n])
__global__ void build_wt(const float* __restrict__ Wr, const float* __restrict__ Wn) {
    int mat = blockIdx.z;
    int l = mat >> 1, s = mat & 1;
    const float* W = (s ? Wn : Wr) + (size_t)l * H * H;
    float* out = g_Wt + (size_t)mat * H * H;
    __shared__ float t[32][33];
    int kx = blockIdx.x * 32, ny = blockIdx.y * 32;
    int tx = threadIdx.x, ty = threadIdx.y;
#pragma unroll
    for (int j = 0; j < 4; j++)
        t[ty + j * 8][tx] = W[(size_t)(kx + ty + j * 8) * H + ny + tx];
    __syncthreads();
#pragma unroll
    for (int j = 0; j < 4; j++) {
        uint32_t r = cvt_tf32(t[tx][ty + j * 8]);
        out[(size_t)(ny + ty + j * 8) * H + kx + tx] = __uint_as_float(r);
    }
}

// ---------------------------------------------------------------------------
// h0 = x @ W_in + b_in
__global__ void in_gemm(const float* __restrict__ x, const float* __restrict__ Win,
                        const float* __restrict__ bin, float* __restrict__ h, int N) {
    __shared__ float xs[16][17];
    int nb = blockIdx.x * 16;
    int tid = threadIdx.x;
    {
        int n = tid >> 4, k = tid & 15;
        int gn = nb + n;
        xs[n][k] = (gn < N) ? x[(size_t)gn * INF + k] : 0.f;
    }
    __syncthreads();
    float w0[16], w1[16];
#pragma unroll
    for (int k = 0; k < 16; k++) {
        w0[k] = Win[k * H + tid];
        w1[k] = Win[k * H + tid + 256];
    }
    float b0 = bin[tid], b1 = bin[tid + 256];
    for (int n = 0; n < 16; n++) {
        int gn = nb + n;
        if (gn >= N) break;
        float a0 = b0, a1 = b1;
#pragma unroll
        for (int k = 0; k < 16; k++) {
            float xv = xs[n][k];
            a0 += xv * w0[k];
            a1 += xv * w1[k];
        }
        h[(size_t)gn * H + tid]       = a0;
        h[(size_t)gn * H + tid + 256] = a1;
    }
}

// ---------------------------------------------------------------------------
// agg[dst] += h[src]
__global__ void scatter(const float* __restrict__ h,
                        const void* __restrict__ ei, int E, const int* __restrict__ flag) {
    int f64 = flag[0];
    int esub = threadIdx.x >> 7;
    int lane = threadIdx.x & 127;
    long e = (long)blockIdx.x * 2 + esub;
    if (e >= E) return;
    long src = ld_idx(ei, e, f64);
    long dst = ld_idx(ei, (long)E + e, f64);
    float4 v = ((const float4*)(h + src * H))[lane];
    red_add_v4(g_agg + dst * H + 4 * lane, v);
}

// ---------------------------------------------------------------------------
// C = A1@W1t' + A2@W2t' + bias via tf32 mma.sync
//   BM=128, BN=128, BK=16, 8 warps (4x2), warp tile 32x64
//   SMEM tiles [128 rows][20 floats] (pad 20 -> conflict-free fragment loads)
#define BM 128
#define BN 128
#define BKT 16
#define ROWSTRIDE 20

__global__ __launch_bounds__(256, 2)
void conv_mma(const float* __restrict__ A1, const float* __restrict__ A2,
              const float* __restrict__ Wt, const float* __restrict__ bias,
              float* __restrict__ C, int M) {
    __shared__ float As[2][BM * ROWSTRIDE];
    __shared__ float Bs[2][BN * ROWSTRIDE];

    int tid = threadIdx.x;
    int wid = tid >> 5, lane = tid & 31;
    int g = lane >> 2, tig = lane & 3;
    int wm0 = (wid & 3) * 32;
    int wn0 = (wid >> 2) * 64;
    int m0 = blockIdx.x * BM;
    int n0 = blockIdx.y * BN;

    // copy mapping: 512 float4 per tile, 2 per thread
    int r0 = tid >> 2, k40 = (tid & 3) * 4;           // chunk 0: rows 0..63
    int r1 = r0 + 64;                                  // chunk 1: rows 64..127

    float4 ga[2], gb[2];
    float acc[2][8][4];
#pragma unroll
    for (int i = 0; i < 2; i++)
#pragma unroll
        for (int j = 0; j < 8; j++)
#pragma unroll
            for (int q = 0; q < 4; q++) acc[i][j][q] = 0.f;

    const int NT = 64;   // 2 sources * 32 BK-tiles

    auto load_g = [&](int t) {
        int s = t >> 5;
        int kt = (t & 31) * BKT;
        const float* A = s ? A2 : A1;
        const float* B = Wt + (size_t)s * H * H;
        int gm0 = m0 + r0, gm1 = m0 + r1;
        ga[0] = (gm0 < M) ? *(const float4*)(A + (size_t)gm0 * H + kt + k40)
                          : make_float4(0.f, 0.f, 0.f, 0.f);
        ga[1] = (gm1 < M) ? *(const float4*)(A + (size_t)gm1 * H + kt + k40)
                          : make_float4(0.f, 0.f, 0.f, 0.f);
        gb[0] = *(const float4*)(B + (size_t)(n0 + r0) * H + kt + k40);
        gb[1] = *(const float4*)(B + (size_t)(n0 + r1) * H + kt + k40);
    };
    auto store_s = [&](int b) {
        float* pa0 = &As[b][r0 * ROWSTRIDE + k40];
        float* pa1 = &As[b][r1 * ROWSTRIDE + k40];
        pa0[0] = __uint_as_float(cvt_tf32(ga[0].x));
        pa0[1] = __uint_as_float(cvt_tf32(ga[0].y));
        pa0[2] = __uint_as_float(cvt_tf32(ga[0].z));
        pa0[3] = __uint_as_float(cvt_tf32(ga[0].w));
        pa1[0] = __uint_as_float(cvt_tf32(ga[1].x));
        pa1[1] = __uint_as_float(cvt_tf32(ga[1].y));
        pa1[2] = __uint_as_float(cvt_tf32(ga[1].z));
        pa1[3] = __uint_as_float(cvt_tf32(ga[1].w));
        *(float4*)&Bs[b][r0 * ROWSTRIDE + k40] = gb[0];
        *(float4*)&Bs[b][r1 * ROWSTRIDE + k40] = gb[1];
    };

    load_g(0);
    store_s(0);
    __syncthreads();

    int buf = 0;
    for (int t = 0; t < NT; t++) {
        if (t + 1 < NT) load_g(t + 1);
#pragma unroll
        for (int ks = 0; ks < 2; ks++) {
            int k = ks * 8;
            uint32_t a[2][4], b[8][2];
#pragma unroll
            for (int i = 0; i < 2; i++) {
                int rb = wm0 + i * 16;
                a[i][0] = __float_as_uint(As[buf][(rb + g) * ROWSTRIDE + k + tig]);
                a[i][1] = __float_as_uint(As[buf][(rb + g + 8) * ROWSTRIDE + k + tig]);
                a[i][2] = __float_as_uint(As[buf][(rb + g) * ROWSTRIDE + k + tig + 4]);
                a[i][3] = __float_as_uint(As[buf][(rb + g + 8) * ROWSTRIDE + k + tig + 4]);
            }
#pragma unroll
            for (int j = 0; j < 8; j++) {
                int nb = wn0 + j * 8;
                b[j][0] = __float_as_uint(Bs[buf][(nb + g) * ROWSTRIDE + k + tig]);
                b[j][1] = __float_as_uint(Bs[buf][(nb + g) * ROWSTRIDE + k + tig + 4]);
            }
#pragma unroll
            for (int i = 0; i < 2; i++)
#pragma unroll
                for (int j = 0; j < 8; j++)
                    mma_tf32(acc[i][j], a[i], b[j]);
        }
        if (t + 1 < NT) store_s(buf ^ 1);
        __syncthreads();
        buf ^= 1;
    }

    // epilogue: add bias, store float2 pairs
#pragma unroll
    for (int i = 0; i < 2; i++) {
        int row0 = m0 + wm0 + i * 16 + g;
        int row1 = row0 + 8;
#pragma unroll
        for (int j = 0; j < 8; j++) {
            int col = n0 + wn0 + j * 8 + tig * 2;
            float bx = bias[col], by = bias[col + 1];
            if (row0 < M) {
                float2 o = make_float2(acc[i][j][0] + bx, acc[i][j][1] + by);
                *(float2*)(C + (size_t)row0 * H + col) = o;
            }
            if (row1 < M) {
                float2 o = make_float2(acc[i][j][2] + bx, acc[i][j][3] + by);
                *(float2*)(C + (size_t)row1 * H + col) = o;
            }
        }
    }
}

// ---------------------------------------------------------------------------
// In-place LayerNorm + ReLU per row
__global__ void ln_relu(float* __restrict__ h, const float* __restrict__ gamma,
                        const float* __restrict__ beta, int N) {
    long row = blockIdx.x;
    if (row >= N) return;
    int tid = threadIdx.x;
    float4 v = *(float4*)(h + row * H + tid * 4);
    float s  = v.x + v.y + v.z + v.w;
    float sq = v.x * v.x + v.y * v.y + v.z * v.z + v.w * v.w;
#pragma unroll
    for (int o = 16; o; o >>= 1) {
        s  += __shfl_xor_sync(~0u, s, o);
        sq += __shfl_xor_sync(~0u, sq, o);
    }
    __shared__ float ss[4], sqs[4];
    int w = tid >> 5;
    if ((tid & 31) == 0) { ss[w] = s; sqs[w] = sq; }
    __syncthreads();
    s  = ss[0] + ss[1] + ss[2] + ss[3];
    sq = sqs[0] + sqs[1] + sqs[2] + sqs[3];
    float mean = s * (1.f / H);
    float var  = sq * (1.f / H) - mean * mean;
    float rstd = rsqrtf(var + 1e-5f);
    int c = tid * 4;
    float4 gm = *(const float4*)(gamma + c);
    float4 bt = *(const float4*)(beta + c);
    v.x = fmaxf((v.x - mean) * rstd * gm.x + bt.x, 0.f);
    v.y = fmaxf((v.y - mean) * rstd * gm.y + bt.y, 0.f);
    v.z = fmaxf((v.z - mean) * rstd * gm.z + bt.z, 0.f);
    v.w = fmaxf((v.w - mean) * rstd * gm.w + bt.w, 0.f);
    *(float4*)(h + row * H + c) = v;
}

// ---------------------------------------------------------------------------
__global__ void pool(const float* __restrict__ h, const void* __restrict__ batch,
                     int N, const int* __restrict__ flag) {
    long n = blockIdx.x;
    if (n >= N) return;
    int f64 = flag[0];
    long g = ld_idx(batch, n, f64);
    int lane = threadIdx.x;
    float4 v = ((const float4*)(h + n * H))[lane];
    red_add_v4(g_pooled + g * H + 4 * lane, v);
    if (lane == 0) atomicAdd(&g_counts[g], 1.f);
}

__global__ void out_gemm(const float* __restrict__ Wout, const float* __restrict__ bout,
                         float* __restrict__ out) {
    int g = blockIdx.x;
    __shared__ float ps[H];
    int tid = threadIdx.x;
    float inv = 1.f / fmaxf(g_counts[g], 1.f);
#pragma unroll
    for (int i = 0; i < 4; i++)
        ps[tid + i * 128] = g_pooled[(size_t)g * H + tid + i * 128] * inv;
    __syncthreads();
    float acc[4];
#pragma unroll
    for (int j = 0; j < 4; j++) acc[j] = bout[tid + j * 128];
    for (int k = 0; k < H; k++) {
        float p = ps[k];
#pragma unroll
        for (int j = 0; j < 4; j++)
            acc[j] += p * Wout[(size_t)k * H + tid + j * 128];
    }
#pragma unroll
    for (int j = 0; j < 4; j++) out[(size_t)g * H + tid + j * 128] = acc[j];
}

// ---------------------------------------------------------------------------
extern "C" void kernel_launch(void* const* d_in, const int* in_sizes, int n_in,
                              void* d_out, int out_size) {
    const float* x      = (const float*)d_in[0];
    const void*  ei     = d_in[1];
    const void*  batch  = d_in[2];
    const float* W_in   = (const float*)d_in[3];
    const float* b_in   = (const float*)d_in[4];
    const float* W_root = (const float*)d_in[5];
    const float* W_neigh= (const float*)d_in[6];
    const float* b_conv = (const float*)d_in[7];
    const float* ln_g   = (const float*)d_in[8];
    const float* ln_b   = (const float*)d_in[9];
    const float* W_out  = (const float*)d_in[10];
    const float* b_out  = (const float*)d_in[11];
    float* out = (float*)d_out;

    int N = in_sizes[0] / INF;
    int E = in_sizes[1] / 2;
    int G = out_size / H;

    void *pA, *pB, *pAgg, *pWt, *pPool, *pCnt, *pFlags;
    cudaGetSymbolAddress(&pA, g_hA);
    cudaGetSymbolAddress(&pB, g_hB);
    cudaGetSymbolAddress(&pAgg, g_agg);
    cudaGetSymbolAddress(&pWt, g_Wt);
    cudaGetSymbolAddress(&pPool, g_pooled);
    cudaGetSymbolAddress(&pCnt, g_counts);
    cudaGetSymbolAddress(&pFlags, g_flags);
    float* hA = (float*)pA;
    float* hB = (float*)pB;
    int* flags = (int*)pFlags;

    cudaMemsetAsync(pFlags, 1, 2 * sizeof(int));
    {
        long nw = in_sizes[1];
        int blocks = (int)((nw / 2 + 255) / 256);
        detect_i64<<<blocks, 256>>>((const int*)ei, nw, flags + 0);
        nw = in_sizes[2];
        blocks = (int)((nw / 2 + 255) / 256);
        detect_i64<<<blocks, 256>>>((const int*)batch, nw, flags + 1);
    }

    {
        dim3 g2(16, 16, 6);
        build_wt<<<g2, dim3(32, 8)>>>(W_root, W_neigh);
    }
    in_gemm<<<(N + 15) / 16, 256>>>(x, W_in, b_in, hA, N);

    float* cur = hA;
    float* nxt = hB;
    for (int l = 0; l < LAYERS; l++) {
        cudaMemsetAsync(pAgg, 0, (size_t)N * H * sizeof(float));
        scatter<<<(E + 1) / 2, 256>>>(cur, ei, E, flags);
        dim3 grid((N + BM - 1) / BM, H / BN);
        conv_mma<<<grid, 256>>>(cur, (const float*)pAgg,
                                (const float*)pWt + (size_t)l * 2 * H * H,
                                b_conv + (size_t)l * H, nxt, N);
        ln_relu<<<N, 128>>>(nxt, ln_g + (size_t)l * H, ln_b + (size_t)l * H, N);
        float* t = cur; cur = nxt; nxt = t;
    }

    cudaMemsetAsync(pPool, 0, (size_t)G * H * sizeof(float));
    cudaMemsetAsync(pCnt, 0, G * sizeof(float));
    pool<<<N, 128>>>(cur, batch, N, flags + 1);
    out_gemm<<<G, 128>>>(W_out, b_out, out);
}

// round 5
// speedup vs baseline: 2.5356x; 1.5281x over previous
#include <cuda_runtime.h>
#include <cstdint>

// ---------------------------------------------------------------------------
// FragmentGraphEncoder: GNN forward
//   tf32 mma.sync conv GEMMs + once-per-call CSR aggregation (no atomics in
//   the per-layer hot path)
// ---------------------------------------------------------------------------

#define H 512
#define INF 16
#define LAYERS 3
#define NMAX 50176
#define GMAX 512
#define EMAX 1048576

__device__ float g_hA[(size_t)NMAX * H];
__device__ float g_hB[(size_t)NMAX * H];
__device__ float g_agg[(size_t)NMAX * H];
__device__ float g_Wt[(size_t)LAYERS * 2 * H * H];   // tf32-rounded, [n][k]
__device__ float g_pooled[GMAX * H];
__device__ float g_counts[GMAX];
__device__ int   g_flags[2];
// CSR scratch
__device__ int   g_deg[NMAX];
__device__ int   g_rowptr[NMAX + 1];
__device__ int   g_cursor[NMAX];
__device__ int   g_col[EMAX];

// ---------------------------------------------------------------------------
__device__ __forceinline__ uint32_t cvt_tf32(float f) {
    uint32_t r; asm("cvt.rna.tf32.f32 %0, %1;" : "=r"(r) : "f"(f)); return r;
}
__device__ __forceinline__ void red_add_v4(float* addr, float4 v) {
    asm volatile("red.global.add.v4.f32 [%0], {%1, %2, %3, %4};"
                 :: "l"(addr), "f"(v.x), "f"(v.y), "f"(v.z), "f"(v.w) : "memory");
}
__device__ __forceinline__ void mma_tf32(float* c, const uint32_t* a, const uint32_t* b) {
    asm("mma.sync.aligned.m16n8k8.row.col.f32.tf32.tf32.f32 "
        "{%0,%1,%2,%3}, {%4,%5,%6,%7}, {%8,%9}, {%0,%1,%2,%3};"
        : "+f"(c[0]), "+f"(c[1]), "+f"(c[2]), "+f"(c[3])
        : "r"(a[0]), "r"(a[1]), "r"(a[2]), "r"(a[3]), "r"(b[0]), "r"(b[1]));
}

// Detect int64 vs int32 index buffers
__global__ void detect_i64(const int* __restrict__ w, long n_words, int* flag) {
    long i = (long)blockIdx.x * blockDim.x + threadIdx.x;
    long idx = 2 * i + 1;
    if (idx < n_words && w[idx] != 0) *flag = 0;
}
__device__ __forceinline__ long ld_idx(const void* p, long i, int f64) {
    return f64 ? (long)((const long long*)p)[i] : (long)((const int*)p)[i];
}

// ---------------------------------------------------------------------------
// CSR build (graph is layer-invariant: build once per call)
__global__ void hist_dst(const void* __restrict__ ei, int E,
                         const int* __restrict__ flag, int* __restrict__ deg) {
    int f64 = flag[0];
    int e = blockIdx.x * blockDim.x + threadIdx.x;
    if (e >= E) return;
    int dst = (int)ld_idx(ei, (long)E + e, f64);
    atomicAdd(&deg[dst], 1);
}

// single-block exclusive scan: rowptr[i] = sum(deg[0..i)), cursor = copy
__global__ void scan_rowptr(const int* __restrict__ deg, int* __restrict__ rowptr,
                            int* __restrict__ cursor, int N) {
    __shared__ int carry;
    __shared__ int wsum[32];
    int tid = threadIdx.x;
    int lane = tid & 31, w = tid >> 5;
    if (tid == 0) carry = 0;
    __syncthreads();
    for (int base = 0; base < N; base += 1024) {
        int i = base + tid;
        int v = (i < N) ? deg[i] : 0;
        int x = v;
#pragma unroll
        for (int o = 1; o < 32; o <<= 1) {
            int t = __shfl_up_sync(~0u, x, o);
            if (lane >= o) x += t;
        }
        if (lane == 31) wsum[w] = x;
        __syncthreads();
        if (w == 0) {
            int s = wsum[lane];
#pragma unroll
            for (int o = 1; o < 32; o <<= 1) {
                int t = __shfl_up_sync(~0u, s, o);
                if (lane >= o) s += t;
            }
            wsum[lane] = s;
        }
        __syncthreads();
        int incl = x + (w ? wsum[w - 1] : 0) + carry;
        if (i < N) {
            rowptr[i] = incl - v;
            cursor[i] = incl - v;
        }
        __syncthreads();
        if (tid == 1023) carry = incl;
        __syncthreads();
    }
    if (tid == 0) rowptr[N] = carry;
}

__global__ void fill_csr(const void* __restrict__ ei, int E,
                         const int* __restrict__ flag,
                         int* __restrict__ cursor, int* __restrict__ col) {
    int f64 = flag[0];
    int e = blockIdx.x * blockDim.x + threadIdx.x;
    if (e >= E) return;
    int src = (int)ld_idx(ei, e, f64);
    int dst = (int)ld_idx(ei, (long)E + e, f64);
    int pos = atomicAdd(&cursor[dst], 1);
    col[pos] = src;
}

// agg[n] = sum_{j in row n} h[col[j]]   (no atomics, writes each elem once)
__global__ void gather_sum(const float* __restrict__ h, const int* __restrict__ rowptr,
                           const int* __restrict__ col, float* __restrict__ agg, int N) {
    int n = blockIdx.x;
    if (n >= N) return;
    int lane = threadIdx.x;                      // 128 threads, float4 each
    int beg = rowptr[n], end = rowptr[n + 1];
    float4 a0 = make_float4(0.f, 0.f, 0.f, 0.f);
    float4 a1 = make_float4(0.f, 0.f, 0.f, 0.f);
    int j = beg;
    for (; j + 2 <= end; j += 2) {
        int s0 = __ldg(col + j);
        int s1 = __ldg(col + j + 1);
        float4 v0 = ((const float4*)(h + (size_t)s0 * H))[lane];
        float4 v1 = ((const float4*)(h + (size_t)s1 * H))[lane];
        a0.x += v0.x; a0.y += v0.y; a0.z += v0.z; a0.w += v0.w;
        a1.x += v1.x; a1.y += v1.y; a1.z += v1.z; a1.w += v1.w;
    }
    if (j < end) {
        int s0 = __ldg(col + j);
        float4 v0 = ((const float4*)(h + (size_t)s0 * H))[lane];
        a0.x += v0.x; a0.y += v0.y; a0.z += v0.z; a0.w += v0.w;
    }
    a0.x += a1.x; a0.y += a1.y; a0.z += a1.z; a0.w += a1.w;
    ((float4*)(agg + (size_t)n * H))[lane] = a0;
}

// ---------------------------------------------------------------------------
// g_Wt[mat][n][k] = rna_tf32(W[mat][k][n])
__global__ void build_wt(const float* __restrict__ Wr, const float* __restrict__ Wn) {
    int mat = blockIdx.z;
    int l = mat >> 1, s = mat & 1;
    const float* W = (s ? Wn : Wr) + (size_t)l * H * H;
    float* out = g_Wt + (size_t)mat * H * H;
    __shared__ float t[32][33];
    int kx = blockIdx.x * 32, ny = blockIdx.y * 32;
    int tx = threadIdx.x, ty = threadIdx.y;
#pragma unroll
    for (int j = 0; j < 4; j++)
        t[ty + j * 8][tx] = W[(size_t)(kx + ty + j * 8) * H + ny + tx];
    __syncthreads();
#pragma unroll
    for (int j = 0; j < 4; j++) {
        uint32_t r = cvt_tf32(t[tx][ty + j * 8]);
        out[(size_t)(ny + ty + j * 8) * H + kx + tx] = __uint_as_float(r);
    }
}

// ---------------------------------------------------------------------------
// h0 = x @ W_in + b_in
__global__ void in_gemm(const float* __restrict__ x, const float* __restrict__ Win,
                        const float* __restrict__ bin, float* __restrict__ h, int N) {
    __shared__ float xs[16][17];
    int nb = blockIdx.x * 16;
    int tid = threadIdx.x;
    {
        int n = tid >> 4, k = tid & 15;
        int gn = nb + n;
        xs[n][k] = (gn < N) ? x[(size_t)gn * INF + k] : 0.f;
    }
    __syncthreads();
    float w0[16], w1[16];
#pragma unroll
    for (int k = 0; k < 16; k++) {
        w0[k] = Win[k * H + tid];
        w1[k] = Win[k * H + tid + 256];
    }
    float b0 = bin[tid], b1 = bin[tid + 256];
    for (int n = 0; n < 16; n++) {
        int gn = nb + n;
        if (gn >= N) break;
        float a0 = b0, a1 = b1;
#pragma unroll
        for (int k = 0; k < 16; k++) {
            float xv = xs[n][k];
            a0 += xv * w0[k];
            a1 += xv * w1[k];
        }
        h[(size_t)gn * H + tid]       = a0;
        h[(size_t)gn * H + tid + 256] = a1;
    }
}

// ---------------------------------------------------------------------------
// C = A1@W1t' + A2@W2t' + bias via tf32 mma.sync
#define BM 128
#define BN 128
#define BKT 16
#define ROWSTRIDE 20

__global__ __launch_bounds__(256, 2)
void conv_mma(const float* __restrict__ A1, const float* __restrict__ A2,
              const float* __restrict__ Wt, const float* __restrict__ bias,
              float* __restrict__ C, int M) {
    __shared__ float As[2][BM * ROWSTRIDE];
    __shared__ float Bs[2][BN * ROWSTRIDE];

    int tid = threadIdx.x;
    int wid = tid >> 5, lane = tid & 31;
    int g = lane >> 2, tig = lane & 3;
    int wm0 = (wid & 3) * 32;
    int wn0 = (wid >> 2) * 64;
    int m0 = blockIdx.x * BM;
    int n0 = blockIdx.y * BN;

    int r0 = tid >> 2, k40 = (tid & 3) * 4;
    int r1 = r0 + 64;

    float4 ga[2], gb[2];
    float acc[2][8][4];
#pragma unroll
    for (int i = 0; i < 2; i++)
#pragma unroll
        for (int j = 0; j < 8; j++)
#pragma unroll
            for (int q = 0; q < 4; q++) acc[i][j][q] = 0.f;

    const int NT = 64;

    auto load_g = [&](int t) {
        int s = t >> 5;
        int kt = (t & 31) * BKT;
        const float* A = s ? A2 : A1;
        const float* B = Wt + (size_t)s * H * H;
        int gm0 = m0 + r0, gm1 = m0 + r1;
        ga[0] = (gm0 < M) ? *(const float4*)(A + (size_t)gm0 * H + kt + k40)
                          : make_float4(0.f, 0.f, 0.f, 0.f);
        ga[1] = (gm1 < M) ? *(const float4*)(A + (size_t)gm1 * H + kt + k40)
                          : make_float4(0.f, 0.f, 0.f, 0.f);
        gb[0] = *(const float4*)(B + (size_t)(n0 + r0) * H + kt + k40);
        gb[1] = *(const float4*)(B + (size_t)(n0 + r1) * H + kt + k40);
    };
    auto store_s = [&](int b) {
        float* pa0 = &As[b][r0 * ROWSTRIDE + k40];
        float* pa1 = &As[b][r1 * ROWSTRIDE + k40];
        pa0[0] = __uint_as_float(cvt_tf32(ga[0].x));
        pa0[1] = __uint_as_float(cvt_tf32(ga[0].y));
        pa0[2] = __uint_as_float(cvt_tf32(ga[0].z));
        pa0[3] = __uint_as_float(cvt_tf32(ga[0].w));
        pa1[0] = __uint_as_float(cvt_tf32(ga[1].x));
        pa1[1] = __uint_as_float(cvt_tf32(ga[1].y));
        pa1[2] = __uint_as_float(cvt_tf32(ga[1].z));
        pa1[3] = __uint_as_float(cvt_tf32(ga[1].w));
        *(float4*)&Bs[b][r0 * ROWSTRIDE + k40] = gb[0];
        *(float4*)&Bs[b][r1 * ROWSTRIDE + k40] = gb[1];
    };

    load_g(0);
    store_s(0);
    __syncthreads();

    int buf = 0;
    for (int t = 0; t < NT; t++) {
        if (t + 1 < NT) load_g(t + 1);
#pragma unroll
        for (int ks = 0; ks < 2; ks++) {
            int k = ks * 8;
            uint32_t a[2][4], b[8][2];
#pragma unroll
            for (int i = 0; i < 2; i++) {
                int rb = wm0 + i * 16;
                a[i][0] = __float_as_uint(As[buf][(rb + g) * ROWSTRIDE + k + tig]);
                a[i][1] = __float_as_uint(As[buf][(rb + g + 8) * ROWSTRIDE + k + tig]);
                a[i][2] = __float_as_uint(As[buf][(rb + g) * ROWSTRIDE + k + tig + 4]);
                a[i][3] = __float_as_uint(As[buf][(rb + g + 8) * ROWSTRIDE + k + tig + 4]);
            }
#pragma unroll
            for (int j = 0; j < 8; j++) {
                int nb = wn0 + j * 8;
                b[j][0] = __float_as_uint(Bs[buf][(nb + g) * ROWSTRIDE + k + tig]);
                b[j][1] = __float_as_uint(Bs[buf][(nb + g) * ROWSTRIDE + k + tig + 4]);
            }
#pragma unroll
            for (int i = 0; i < 2; i++)
#pragma unroll
                for (int j = 0; j < 8; j++)
                    mma_tf32(acc[i][j], a[i], b[j]);
        }
        if (t + 1 < NT) store_s(buf ^ 1);
        __syncthreads();
        buf ^= 1;
    }

#pragma unroll
    for (int i = 0; i < 2; i++) {
        int row0 = m0 + wm0 + i * 16 + g;
        int row1 = row0 + 8;
#pragma unroll
        for (int j = 0; j < 8; j++) {
            int col = n0 + wn0 + j * 8 + tig * 2;
            float bx = bias[col], by = bias[col + 1];
            if (row0 < M) {
                float2 o = make_float2(acc[i][j][0] + bx, acc[i][j][1] + by);
                *(float2*)(C + (size_t)row0 * H + col) = o;
            }
            if (row1 < M) {
                float2 o = make_float2(acc[i][j][2] + bx, acc[i][j][3] + by);
                *(float2*)(C + (size_t)row1 * H + col) = o;
            }
        }
    }
}

// ---------------------------------------------------------------------------
// In-place LayerNorm + ReLU per row
__global__ void ln_relu(float* __restrict__ h, const float* __restrict__ gamma,
                        const float* __restrict__ beta, int N) {
    long row = blockIdx.x;
    if (row >= N) return;
    int tid = threadIdx.x;
    float4 v = *(float4*)(h + row * H + tid * 4);
    float s  = v.x + v.y + v.z + v.w;
    float sq = v.x * v.x + v.y * v.y + v.z * v.z + v.w * v.w;
#pragma unroll
    for (int o = 16; o; o >>= 1) {
        s  += __shfl_xor_sync(~0u, s, o);
        sq += __shfl_xor_sync(~0u, sq, o);
    }
    __shared__ float ss[4], sqs[4];
    int w = tid >> 5;
    if ((tid & 31) == 0) { ss[w] = s; sqs[w] = sq; }
    __syncthreads();
    s  = ss[0] + ss[1] + ss[2] + ss[3];
    sq = sqs[0] + sqs[1] + sqs[2] + sqs[3];
    float mean = s * (1.f / H);
    float var  = sq * (1.f / H) - mean * mean;
    float rstd = rsqrtf(var + 1e-5f);
    int c = tid * 4;
    float4 gm = *(const float4*)(gamma + c);
    float4 bt = *(const float4*)(beta + c);
    v.x = fmaxf((v.x - mean) * rstd * gm.x + bt.x, 0.f);
    v.y = fmaxf((v.y - mean) * rstd * gm.y + bt.y, 0.f);
    v.z = fmaxf((v.z - mean) * rstd * gm.z + bt.z, 0.f);
    v.w = fmaxf((v.w - mean) * rstd * gm.w + bt.w, 0.f);
    *(float4*)(h + row * H + c) = v;
}

// ---------------------------------------------------------------------------
__global__ void pool(const float* __restrict__ h, const void* __restrict__ batch,
                     int N, const int* __restrict__ flag) {
    long n = blockIdx.x;
    if (n >= N) return;
    int f64 = flag[0];
    long g = ld_idx(batch, n, f64);
    int lane = threadIdx.x;
    float4 v = ((const float4*)(h + n * H))[lane];
    red_add_v4(g_pooled + g * H + 4 * lane, v);
    if (lane == 0) atomicAdd(&g_counts[g], 1.f);
}

__global__ void out_gemm(const float* __restrict__ Wout, const float* __restrict__ bout,
                         float* __restrict__ out) {
    int g = blockIdx.x;
    __shared__ float ps[H];
    int tid = threadIdx.x;
    float inv = 1.f / fmaxf(g_counts[g], 1.f);
#pragma unroll
    for (int i = 0; i < 4; i++)
        ps[tid + i * 128] = g_pooled[(size_t)g * H + tid + i * 128] * inv;
    __syncthreads();
    float acc[4];
#pragma unroll
    for (int j = 0; j < 4; j++) acc[j] = bout[tid + j * 128];
    for (int k = 0; k < H; k++) {
        float p = ps[k];
#pragma unroll
        for (int j = 0; j < 4; j++)
            acc[j] += p * Wout[(size_t)k * H + tid + j * 128];
    }
#pragma unroll
    for (int j = 0; j < 4; j++) out[(size_t)g * H + tid + j * 128] = acc[j];
}

// ---------------------------------------------------------------------------
extern "C" void kernel_launch(void* const* d_in, const int* in_sizes, int n_in,
                              void* d_out, int out_size) {
    const float* x      = (const float*)d_in[0];
    const void*  ei     = d_in[1];
    const void*  batch  = d_in[2];
    const float* W_in   = (const float*)d_in[3];
    const float* b_in   = (const float*)d_in[4];
    const float* W_root = (const float*)d_in[5];
    const float* W_neigh= (const float*)d_in[6];
    const float* b_conv = (const float*)d_in[7];
    const float* ln_g   = (const float*)d_in[8];
    const float* ln_b   = (const float*)d_in[9];
    const float* W_out  = (const float*)d_in[10];
    const float* b_out  = (const float*)d_in[11];
    float* out = (float*)d_out;

    int N = in_sizes[0] / INF;
    int E = in_sizes[1] / 2;
    int G = out_size / H;

    void *pA, *pB, *pAgg, *pWt, *pPool, *pCnt, *pFlags;
    void *pDeg, *pRow, *pCur, *pCol;
    cudaGetSymbolAddress(&pA, g_hA);
    cudaGetSymbolAddress(&pB, g_hB);
    cudaGetSymbolAddress(&pAgg, g_agg);
    cudaGetSymbolAddress(&pWt, g_Wt);
    cudaGetSymbolAddress(&pPool, g_pooled);
    cudaGetSymbolAddress(&pCnt, g_counts);
    cudaGetSymbolAddress(&pFlags, g_flags);
    cudaGetSymbolAddress(&pDeg, g_deg);
    cudaGetSymbolAddress(&pRow, g_rowptr);
    cudaGetSymbolAddress(&pCur, g_cursor);
    cudaGetSymbolAddress(&pCol, g_col);
    float* hA = (float*)pA;
    float* hB = (float*)pB;
    int* flags = (int*)pFlags;

    cudaMemsetAsync(pFlags, 1, 2 * sizeof(int));
    {
        long nw = in_sizes[1];
        int blocks = (int)((nw / 2 + 255) / 256);
        detect_i64<<<blocks, 256>>>((const int*)ei, nw, flags + 0);
        nw = in_sizes[2];
        blocks = (int)((nw / 2 + 255) / 256);
        detect_i64<<<blocks, 256>>>((const int*)batch, nw, flags + 1);
    }

    // CSR build (once per call; graph identical across layers)
    cudaMemsetAsync(pDeg, 0, (size_t)N * sizeof(int));
    hist_dst<<<(E + 255) / 256, 256>>>(ei, E, flags, (int*)pDeg);
    scan_rowptr<<<1, 1024>>>((const int*)pDeg, (int*)pRow, (int*)pCur, N);
    fill_csr<<<(E + 255) / 256, 256>>>(ei, E, flags, (int*)pCur, (int*)pCol);

    {
        dim3 g2(16, 16, 6);
        build_wt<<<g2, dim3(32, 8)>>>(W_root, W_neigh);
    }
    in_gemm<<<(N + 15) / 16, 256>>>(x, W_in, b_in, hA, N);

    float* cur = hA;
    float* nxt = hB;
    for (int l = 0; l < LAYERS; l++) {
        gather_sum<<<N, 128>>>(cur, (const int*)pRow, (const int*)pCol,
                               (float*)pAgg, N);
        dim3 grid((N + BM - 1) / BM, H / BN);
        conv_mma<<<grid, 256>>>(cur, (const float*)pAgg,
                                (const float*)pWt + (size_t)l * 2 * H * H,
                                b_conv + (size_t)l * H, nxt, N);
        ln_relu<<<N, 128>>>(nxt, ln_g + (size_t)l * H, ln_b + (size_t)l * H, N);
        float* t = cur; cur = nxt; nxt = t;
    }

    cudaMemsetAsync(pPool, 0, (size_t)G * H * sizeof(float));
    cudaMemsetAsync(pCnt, 0, G * sizeof(float));
    pool<<<N, 128>>>(cur, batch, N, flags + 1);
    out_gemm<<<G, 128>>>(W_out, b_out, out);
}

// round 7
// speedup vs baseline: 2.8578x; 1.1271x over previous
#include <cuda_runtime.h>
#include <cstdint>

// ---------------------------------------------------------------------------
// FragmentGraphEncoder: GNN forward
//   tf32 mma.sync conv GEMMs (cp.async 3-stage pipeline) + CSR aggregation
//   Activations pre-rounded to tf32 by producers.
// ---------------------------------------------------------------------------

#define H 512
#define INF 16
#define LAYERS 3
#define NMAX 50176
#define GMAX 512
#define EMAX 1048576

__device__ float g_hA[(size_t)NMAX * H];
__device__ float g_hB[(size_t)NMAX * H];
__device__ float g_agg[(size_t)NMAX * H];
__device__ float g_Wt[(size_t)LAYERS * 2 * H * H];   // tf32-rounded, [n][k]
__device__ float g_pooled[GMAX * H];
__device__ float g_counts[GMAX];
__device__ int   g_flags[2];
// CSR scratch
__device__ int   g_deg[NMAX];
__device__ int   g_rowptr[NMAX + 1];
__device__ int   g_cursor[NMAX];
__device__ int   g_csums[64];
__device__ int   g_col[EMAX];

// ---------------------------------------------------------------------------
__device__ __forceinline__ uint32_t cvt_tf32(float f) {
    uint32_t r; asm("cvt.rna.tf32.f32 %0, %1;" : "=r"(r) : "f"(f)); return r;
}
__device__ __forceinline__ float rtf(float f) { return __uint_as_float(cvt_tf32(f)); }
__device__ __forceinline__ void red_add_v4(float* addr, float4 v) {
    asm volatile("red.global.add.v4.f32 [%0], {%1, %2, %3, %4};"
                 :: "l"(addr), "f"(v.x), "f"(v.y), "f"(v.z), "f"(v.w) : "memory");
}
__device__ __forceinline__ void mma_tf32(float* c, const uint32_t* a, const uint32_t* b) {
    asm("mma.sync.aligned.m16n8k8.row.col.f32.tf32.tf32.f32 "
        "{%0,%1,%2,%3}, {%4,%5,%6,%7}, {%8,%9}, {%0,%1,%2,%3};"
        : "+f"(c[0]), "+f"(c[1]), "+f"(c[2]), "+f"(c[3])
        : "r"(a[0]), "r"(a[1]), "r"(a[2]), "r"(a[3]), "r"(b[0]), "r"(b[1]));
}
__device__ __forceinline__ uint32_t smem_u32(const void* p) {
    uint32_t a;
    asm("{ .reg .u64 t; cvta.to.shared.u64 t, %1; cvt.u32.u64 %0, t; }" : "=r"(a) : "l"(p));
    return a;
}
__device__ __forceinline__ void cp_async16(uint32_t dst, const void* src) {
    asm volatile("cp.async.cg.shared.global [%0], [%1], 16;" :: "r"(dst), "l"(src));
}

// Detect int64 vs int32 index buffers
__global__ void detect_i64(const int* __restrict__ w, long n_words, int* flag) {
    long i = (long)blockIdx.x * blockDim.x + threadIdx.x;
    long idx = 2 * i + 1;
    if (idx < n_words && w[idx] != 0) *flag = 0;
}
__device__ __forceinline__ long ld_idx(const void* p, long i, int f64) {
    return f64 ? (long)((const long long*)p)[i] : (long)((const int*)p)[i];
}

// ---------------------------------------------------------------------------
// CSR build (graph is layer-invariant: build once per call)
__global__ void hist_dst(const void* __restrict__ ei, int E,
                         const int* __restrict__ flag, int* __restrict__ deg) {
    int f64 = flag[0];
    int e = blockIdx.x * blockDim.x + threadIdx.x;
    if (e >= E) return;
    int dst = (int)ld_idx(ei, (long)E + e, f64);
    atomicAdd(&deg[dst], 1);
}

// per-1024-chunk sums
__global__ void chunk_sums(const int* __restrict__ deg, int* __restrict__ sums, int N) {
    __shared__ int ws[8];
    int base = blockIdx.x << 10;
    int tid = threadIdx.x;            // 256
    int v = 0;
#pragma unroll
    for (int i = 0; i < 4; i++) {
        int idx = base + tid + i * 256;
        v += (idx < N) ? deg[idx] : 0;
    }
#pragma unroll
    for (int o = 16; o; o >>= 1) v += __shfl_xor_sync(~0u, v, o);
    if ((tid & 31) == 0) ws[tid >> 5] = v;
    __syncthreads();
    if (tid == 0) {
        int s = 0;
#pragma unroll
        for (int i = 0; i < 8; i++) s += ws[i];
        sums[blockIdx.x] = s;
    }
}

// exclusive scan of <=64 chunk sums in one warp; also writes rowptr[N]=E
__global__ void scan_sums(int* __restrict__ sums, int* __restrict__ rowptr,
                          int nchunks, int N, int E) {
    int lane = threadIdx.x;
    int v0 = (lane < nchunks) ? sums[lane] : 0;
    int v1 = (lane + 32 < nchunks) ? sums[lane + 32] : 0;
    int x0 = v0;
#pragma unroll
    for (int o = 1; o < 32; o <<= 1) {
        int t = __shfl_up_sync(~0u, x0, o);
        if (lane >= o) x0 += t;
    }
    int tot0 = __shfl_sync(~0u, x0, 31);
    int x1 = v1;
#pragma unroll
    for (int o = 1; o < 32; o <<= 1) {
        int t = __shfl_up_sync(~0u, x1, o);
        if (lane >= o) x1 += t;
    }
    x1 += tot0;
    if (lane < nchunks) sums[lane] = x0 - v0;
    if (lane + 32 < nchunks) sums[lane + 32] = x1 - v1;
    if (lane == 0) rowptr[N] = E;
}

// local 1024-scan per chunk + chunk offset
__global__ void scan_chunks(const int* __restrict__ deg, const int* __restrict__ csums,
                            int* __restrict__ rowptr, int* __restrict__ cursor, int N) {
    __shared__ int wsum[32];
    int base = blockIdx.x << 10;
    int tid = threadIdx.x, lane = tid & 31, w = tid >> 5;
    int i = base + tid;
    int v = (i < N) ? deg[i] : 0;
    int x = v;
#pragma unroll
    for (int o = 1; o < 32; o <<= 1) {
        int t = __shfl_up_sync(~0u, x, o);
        if (lane >= o) x += t;
    }
    if (lane == 31) wsum[w] = x;
    __syncthreads();
    if (w == 0) {
        int s = wsum[lane];
#pragma unroll
        for (int o = 1; o < 32; o <<= 1) {
            int t = __shfl_up_sync(~0u, s, o);
            if (lane >= o) s += t;
        }
        wsum[lane] = s;
    }
    __syncthreads();
    int excl = x - v + (w ? wsum[w - 1] : 0) + csums[blockIdx.x];
    if (i < N) { rowptr[i] = excl; cursor[i] = excl; }
}

__global__ void fill_csr(const void* __restrict__ ei, int E,
                         const int* __restrict__ flag,
                         int* __restrict__ cursor, int* __restrict__ col) {
    int f64 = flag[0];
    int e = blockIdx.x * blockDim.x + threadIdx.x;
    if (e >= E) return;
    int src = (int)ld_idx(ei, e, f64);
    int dst = (int)ld_idx(ei, (long)E + e, f64);
    int pos = atomicAdd(&cursor[dst], 1);
    col[pos] = src;
}

// agg[n] = tf32_round(sum_{j in row n} h[col[j]])
__global__ void gather_sum(const float* __restrict__ h, const int* __restrict__ rowptr,
                           const int* __restrict__ col, float* __restrict__ agg, int N) {
    int n = blockIdx.x;
    if (n >= N) return;
    int lane = threadIdx.x;                      // 128 threads, float4 each
    int beg = rowptr[n], end = rowptr[n + 1];
    float4 a0 = make_float4(0.f, 0.f, 0.f, 0.f);
    float4 a1 = make_float4(0.f, 0.f, 0.f, 0.f);
    int j = beg;
    for (; j + 2 <= end; j += 2) {
        int s0 = __ldg(col + j);
        int s1 = __ldg(col + j + 1);
        float4 v0 = ((const float4*)(h + (size_t)s0 * H))[lane];
        float4 v1 = ((const float4*)(h + (size_t)s1 * H))[lane];
        a0.x += v0.x; a0.y += v0.y; a0.z += v0.z; a0.w += v0.w;
        a1.x += v1.x; a1.y += v1.y; a1.z += v1.z; a1.w += v1.w;
    }
    if (j < end) {
        int s0 = __ldg(col + j);
        float4 v0 = ((const float4*)(h + (size_t)s0 * H))[lane];
        a0.x += v0.x; a0.y += v0.y; a0.z += v0.z; a0.w += v0.w;
    }
    a0.x = rtf(a0.x + a1.x); a0.y = rtf(a0.y + a1.y);
    a0.z = rtf(a0.z + a1.z); a0.w = rtf(a0.w + a1.w);
    ((float4*)(agg + (size_t)n * H))[lane] = a0;
}

// ---------------------------------------------------------------------------
// g_Wt[mat][n][k] = rna_tf32(W[mat][k][n])
__global__ void build_wt(const float* __restrict__ Wr, const float* __restrict__ Wn) {
    int mat = blockIdx.z;
    int l = mat >> 1, s = mat & 1;
    const float* W = (s ? Wn : Wr) + (size_t)l * H * H;
    float* out = g_Wt + (size_t)mat * H * H;
    __shared__ float t[32][33];
    int kx = blockIdx.x * 32, ny = blockIdx.y * 32;
    int tx = threadIdx.x, ty = threadIdx.y;
#pragma unroll
    for (int j = 0; j < 4; j++)
        t[ty + j * 8][tx] = W[(size_t)(kx + ty + j * 8) * H + ny + tx];
    __syncthreads();
#pragma unroll
    for (int j = 0; j < 4; j++)
        out[(size_t)(ny + ty + j * 8) * H + kx + tx] = rtf(t[tx][ty + j * 8]);
}

// ---------------------------------------------------------------------------
// h0 = tf32_round(x @ W_in + b_in)
__global__ void in_gemm(const float* __restrict__ x, const float* __restrict__ Win,
                        const float* __restrict__ bin, float* __restrict__ h, int N) {
    __shared__ float xs[16][17];
    int nb = blockIdx.x * 16;
    int tid = threadIdx.x;
    {
        int n = tid >> 4, k = tid & 15;
        int gn = nb + n;
        xs[n][k] = (gn < N) ? x[(size_t)gn * INF + k] : 0.f;
    }
    __syncthreads();
    float w0[16], w1[16];
#pragma unroll
    for (int k = 0; k < 16; k++) {
        w0[k] = Win[k * H + tid];
        w1[k] = Win[k * H + tid + 256];
    }
    float b0 = bin[tid], b1 = bin[tid + 256];
    for (int n = 0; n < 16; n++) {
        int gn = nb + n;
        if (gn >= N) break;
        float a0 = b0, a1 = b1;
#pragma unroll
        for (int k = 0; k < 16; k++) {
            float xv = xs[n][k];
            a0 += xv * w0[k];
            a1 += xv * w1[k];
        }
        h[(size_t)gn * H + tid]       = rtf(a0);
        h[(size_t)gn * H + tid + 256] = rtf(a1);
    }
}

// ---------------------------------------------------------------------------
// C = A1@W1t' + A2@W2t' + bias via tf32 mma.sync, cp.async 3-stage pipeline
//   BM=128, BN=128, BK=16, 8 warps (4x2), warp tile 32x64
//   SMEM [row][20 floats] padded rows (80B, 16B-aligned), conflict-free frags
#define BM 128
#define BN 128
#define BKT 16
#define ROWSTRIDE 20
#define STAGES 3
#define TILE_FLOATS (BM * ROWSTRIDE)            // per-tile floats (A or B)
#define CONV_SMEM (STAGES * 2 * TILE_FLOATS * 4)

__global__ __launch_bounds__(256, 2)
void conv_mma(const float* __restrict__ A1, const float* __restrict__ A2,
              const float* __restrict__ Wt, const float* __restrict__ bias,
              float* __restrict__ C, int M) {
    extern __shared__ float smp[];
    float* As = smp;                              // STAGES * TILE_FLOATS
    float* Bs = smp + STAGES * TILE_FLOATS;
    uint32_t aAddr = smem_u32(As);
    uint32_t bAddr = smem_u32(Bs);

    int tid = threadIdx.x;
    int wid = tid >> 5, lane = tid & 31;
    int g = lane >> 2, tig = lane & 3;
    int wm0 = (wid & 3) * 32;
    int wn0 = (wid >> 2) * 64;
    int m0 = blockIdx.x * BM;
    int n0 = blockIdx.y * BN;

    int cprow = tid >> 2;                         // 0..63
    int cpseg = (tid & 3) * 16;                   // byte seg within 64B row

    float acc[2][8][4];
#pragma unroll
    for (int i = 0; i < 2; i++)
#pragma unroll
        for (int j = 0; j < 8; j++)
#pragma unroll
            for (int q = 0; q < 4; q++) acc[i][j][q] = 0.f;

    const int NT = 64;                            // 2 sources * 32 BK-tiles

    auto issue = [&](int t) {
        int st = t % STAGES;
        int s = t >> 5;
        int kt = (t & 31) * BKT;
        const float* A = s ? A2 : A1;             // rows < NMAX always valid
        const float* B = Wt + (size_t)s * H * H;
        uint32_t ab = aAddr + st * (TILE_FLOATS * 4);
        uint32_t bb = bAddr + st * (TILE_FLOATS * 4);
        cp_async16(ab + cprow * 80 + cpseg,
                   A + (size_t)(m0 + cprow) * H + kt + (cpseg >> 2));
        cp_async16(ab + (cprow + 64) * 80 + cpseg,
                   A + (size_t)(m0 + cprow + 64) * H + kt + (cpseg >> 2));
        cp_async16(bb + cprow * 80 + cpseg,
                   B + (size_t)(n0 + cprow) * H + kt + (cpseg >> 2));
        cp_async16(bb + (cprow + 64) * 80 + cpseg,
                   B + (size_t)(n0 + cprow + 64) * H + kt + (cpseg >> 2));
        asm volatile("cp.async.commit_group;" ::: "memory");
    };

    issue(0);
    issue(1);

    for (int t = 0; t < NT; t++) {
        if (t + 1 < NT) {
            asm volatile("cp.async.wait_group 1;" ::: "memory");
        } else {
            asm volatile("cp.async.wait_group 0;" ::: "memory");
        }
        __syncthreads();
        if (t + 2 < NT) issue(t + 2);

        const float* Asb = As + (t % STAGES) * TILE_FLOATS;
        const float* Bsb = Bs + (t % STAGES) * TILE_FLOATS;
#pragma unroll
        for (int ks = 0; ks < 2; ks++) {
            int k = ks * 8;
            uint32_t a[2][4], b[8][2];
#pragma unroll
            for (int i = 0; i < 2; i++) {
                int rb = wm0 + i * 16;
                a[i][0] = __float_as_uint(Asb[(rb + g) * ROWSTRIDE + k + tig]);
                a[i][1] = __float_as_uint(Asb[(rb + g + 8) * ROWSTRIDE + k + tig]);
                a[i][2] = __float_as_uint(Asb[(rb + g) * ROWSTRIDE + k + tig + 4]);
                a[i][3] = __float_as_uint(Asb[(rb + g + 8) * ROWSTRIDE + k + tig + 4]);
            }
#pragma unroll
            for (int j = 0; j < 8; j++) {
                int nb = wn0 + j * 8;
                b[j][0] = __float_as_uint(Bsb[(nb + g) * ROWSTRIDE + k + tig]);
                b[j][1] = __float_as_uint(Bsb[(nb + g) * ROWSTRIDE + k + tig + 4]);
            }
#pragma unroll
            for (int i = 0; i < 2; i++)
#pragma unroll
                for (int j = 0; j < 8; j++)
                    mma_tf32(acc[i][j], a[i], b[j]);
        }
    }

    // epilogue: add bias, store float2 pairs
#pragma unroll
    for (int i = 0; i < 2; i++) {
        int row0 = m0 + wm0 + i * 16 + g;
        int row1 = row0 + 8;
#pragma unroll
        for (int j = 0; j < 8; j++) {
            int col = n0 + wn0 + j * 8 + tig * 2;
            float bx = bias[col], by = bias[col + 1];
            if (row0 < M) {
                float2 o = make_float2(acc[i][j][0] + bx, acc[i][j][1] + by);
                *(float2*)(C + (size_t)row0 * H + col) = o;
            }
            if (row1 < M) {
                float2 o = make_float2(acc[i][j][2] + bx, acc[i][j][3] + by);
                *(float2*)(C + (size_t)row1 * H + col) = o;
            }
        }
    }
}

// ---------------------------------------------------------------------------
// In-place LayerNorm + ReLU per row (outputs tf32-rounded)
__global__ void ln_relu(float* __restrict__ h, const float* __restrict__ gamma,
                        const float* __restrict__ beta, int N) {
    long row = blockIdx.x;
    if (row >= N) return;
    int tid = threadIdx.x;
    float4 v = *(float4*)(h + row * H + tid * 4);
    float s  = v.x + v.y + v.z + v.w;
    float sq = v.x * v.x + v.y * v.y + v.z * v.z + v.w * v.w;
#pragma unroll
    for (int o = 16; o; o >>= 1) {
        s  += __shfl_xor_sync(~0u, s, o);
        sq += __shfl_xor_sync(~0u, sq, o);
    }
    __shared__ float ss[4], sqs[4];
    int w = tid >> 5;
    if ((tid & 31) == 0) { ss[w] = s; sqs[w] = sq; }
    __syncthreads();
    s  = ss[0] + ss[1] + ss[2] + ss[3];
    sq = sqs[0] + sqs[1] + sqs[2] + sqs[3];
    float mean = s * (1.f / H);
    float var  = sq * (1.f / H) - mean * mean;
    float rstd = rsqrtf(var + 1e-5f);
    int c = tid * 4;
    float4 gm = *(const float4*)(gamma + c);
    float4 bt = *(const float4*)(beta + c);
    v.x = rtf(fmaxf((v.x - mean) * rstd * gm.x + bt.x, 0.f));
    v.y = rtf(fmaxf((v.y - mean) * rstd * gm.y + bt.y, 0.f));
    v.z = rtf(fmaxf((v.z - mean) * rstd * gm.z + bt.z, 0.f));
    v.w = rtf(fmaxf((v.w - mean) * rstd * gm.w + bt.w, 0.f));
    *(float4*)(h + row * H + c) = v;
}

// ---------------------------------------------------------------------------
__global__ void pool(const float* __restrict__ h, const void* __restrict__ batch,
                     int N, const int* __restrict__ flag) {
    long n = blockIdx.x;
    if (n >= N) return;
    int f64 = flag[0];
    long g = ld_idx(batch, n, f64);
    int lane = threadIdx.x;
    float4 v = ((const float4*)(h + n * H))[lane];
    red_add_v4(g_pooled + g * H + 4 * lane, v);
    if (lane == 0) atomicAdd(&g_counts[g], 1.f);
}

__global__ void out_gemm(const float* __restrict__ Wout, const float* __restrict__ bout,
                         float* __restrict__ out) {
    int g = blockIdx.x;
    __shared__ float ps[H];
    int tid = threadIdx.x;
    float inv = 1.f / fmaxf(g_counts[g], 1.f);
#pragma unroll
    for (int i = 0; i < 4; i++)
        ps[tid + i * 128] = g_pooled[(size_t)g * H + tid + i * 128] * inv;
    __syncthreads();
    float acc[4];
#pragma unroll
    for (int j = 0; j < 4; j++) acc[j] = bout[tid + j * 128];
    for (int k = 0; k < H; k++) {
        float p = ps[k];
#pragma unroll
        for (int j = 0; j < 4; j++)
            acc[j] += p * Wout[(size_t)k * H + tid + j * 128];
    }
#pragma unroll
    for (int j = 0; j < 4; j++) out[(size_t)g * H + tid + j * 128] = acc[j];
}

// ---------------------------------------------------------------------------
extern "C" void kernel_launch(void* const* d_in, const int* in_sizes, int n_in,
                              void* d_out, int out_size) {
    const float* x      = (const float*)d_in[0];
    const void*  ei     = d_in[1];
    const void*  batch  = d_in[2];
    const float* W_in   = (const float*)d_in[3];
    const float* b_in   = (const float*)d_in[4];
    const float* W_root = (const float*)d_in[5];
    const float* W_neigh= (const float*)d_in[6];
    const float* b_conv = (const float*)d_in[7];
    const float* ln_g   = (const float*)d_in[8];
    const float* ln_b   = (const float*)d_in[9];
    const float* W_out  = (const float*)d_in[10];
    const float* b_out  = (const float*)d_in[11];
    float* out = (float*)d_out;

    int N = in_sizes[0] / INF;
    int E = in_sizes[1] / 2;
    int G = out_size / H;
    int nchunks = (N + 1023) / 1024;

    void *pA, *pB, *pAgg, *pWt, *pPool, *pCnt, *pFlags;
    void *pDeg, *pRow, *pCur, *pCsums, *pCol;
    cudaGetSymbolAddress(&pA, g_hA);
    cudaGetSymbolAddress(&pB, g_hB);
    cudaGetSymbolAddress(&pAgg, g_agg);
    cudaGetSymbolAddress(&pWt, g_Wt);
    cudaGetSymbolAddress(&pPool, g_pooled);
    cudaGetSymbolAddress(&pCnt, g_counts);
    cudaGetSymbolAddress(&pFlags, g_flags);
    cudaGetSymbolAddress(&pDeg, g_deg);
    cudaGetSymbolAddress(&pRow, g_rowptr);
    cudaGetSymbolAddress(&pCur, g_cursor);
    cudaGetSymbolAddress(&pCsums, g_csums);
    cudaGetSymbolAddress(&pCol, g_col);
    float* hA = (float*)pA;
    float* hB = (float*)pB;
    int* flags = (int*)pFlags;

    cudaFuncSetAttribute(conv_mma, cudaFuncAttributeMaxDynamicSharedMemorySize, CONV_SMEM);

    cudaMemsetAsync(pFlags, 1, 2 * sizeof(int));
    {
        long nw = in_sizes[1];
        int blocks = (int)((nw / 2 + 255) / 256);
        detect_i64<<<blocks, 256>>>((const int*)ei, nw, flags + 0);
        nw = in_sizes[2];
        blocks = (int)((nw / 2 + 255) / 256);
        detect_i64<<<blocks, 256>>>((const int*)batch, nw, flags + 1);
    }

    // CSR build (once per call; graph identical across layers)
    cudaMemsetAsync(pDeg, 0, (size_t)N * sizeof(int));
    hist_dst<<<(E + 255) / 256, 256>>>(ei, E, flags, (int*)pDeg);
    chunk_sums<<<nchunks, 256>>>((const int*)pDeg, (int*)pCsums, N);
    scan_sums<<<1, 32>>>((int*)pCsums, (int*)pRow, nchunks, N, E);
    scan_chunks<<<nchunks, 1024>>>((const int*)pDeg, (const int*)pCsums,
                                   (int*)pRow, (int*)pCur, N);
    fill_csr<<<(E + 255) / 256, 256>>>(ei, E, flags, (int*)pCur, (int*)pCol);

    {
        dim3 g2(16, 16, 6);
        build_wt<<<g2, dim3(32, 8)>>>(W_root, W_neigh);
    }
    in_gemm<<<(N + 15) / 16, 256>>>(x, W_in, b_in, hA, N);

    float* cur = hA;
    float* nxt = hB;
    for (int l = 0; l < LAYERS; l++) {
        gather_sum<<<N, 128>>>(cur, (const int*)pRow, (const int*)pCol,
                               (float*)pAgg, N);
        dim3 grid((N + BM - 1) / BM, H / BN);
        conv_mma<<<grid, 256, CONV_SMEM>>>(cur, (const float*)pAgg,
                                           (const float*)pWt + (size_t)l * 2 * H * H,
                                           b_conv + (size_t)l * H, nxt, N);
        ln_relu<<<N, 128>>>(nxt, ln_g + (size_t)l * H, ln_b + (size_t)l * H, N);
        float* t = cur; cur = nxt; nxt = t;
    }

    cudaMemsetAsync(pPool, 0, (size_t)G * H * sizeof(float));
    cudaMemsetAsync(pCnt, 0, G * sizeof(float));
    pool<<<N, 128>>>(cur, batch, N, flags + 1);
    out_gemm<<<G, 128>>>(W_out, b_out, out);
}

// round 9
// speedup vs baseline: 4.3065x; 1.5069x over previous
#include <cuda_runtime.h>
#include <cuda_fp16.h>
#include <cstdint>

// ---------------------------------------------------------------------------
// FragmentGraphEncoder: GNN forward
//   fp16 mma.sync (m16n8k16) conv GEMMs, fp16 activation storage, fp32 accum
//   cp.async 3-stage pipeline + once-per-call CSR aggregation
// ---------------------------------------------------------------------------

#define H 512
#define INF 16
#define LAYERS 3
#define NMAX 50176
#define GMAX 512
#define EMAX 1048576

__device__ __half g_hA[(size_t)NMAX * H];
__device__ __half g_hB[(size_t)NMAX * H];
__device__ __half g_agg[(size_t)NMAX * H];
__device__ __half g_Wt[(size_t)LAYERS * 2 * H * H];   // fp16, [n][k]
__device__ float  g_pooled[GMAX * H];
__device__ float  g_counts[GMAX];
__device__ int    g_flags[2];
// CSR scratch
__device__ int    g_deg[NMAX];
__device__ int    g_rowptr[NMAX + 1];
__device__ int    g_cursor[NMAX];
__device__ int    g_csums[64];
__device__ int    g_col[EMAX];

// ---------------------------------------------------------------------------
__device__ __forceinline__ void red_add_v4(float* addr, float4 v) {
    asm volatile("red.global.add.v4.f32 [%0], {%1, %2, %3, %4};"
                 :: "l"(addr), "f"(v.x), "f"(v.y), "f"(v.z), "f"(v.w) : "memory");
}
__device__ __forceinline__ void mma_f16(float* c, const uint32_t* a, const uint32_t* b) {
    asm("mma.sync.aligned.m16n8k16.row.col.f32.f16.f16.f32 "
        "{%0,%1,%2,%3}, {%4,%5,%6,%7}, {%8,%9}, {%0,%1,%2,%3};"
        : "+f"(c[0]), "+f"(c[1]), "+f"(c[2]), "+f"(c[3])
        : "r"(a[0]), "r"(a[1]), "r"(a[2]), "r"(a[3]), "r"(b[0]), "r"(b[1]));
}
__device__ __forceinline__ uint32_t smem_u32(const void* p) {
    uint32_t a;
    asm("{ .reg .u64 t; cvta.to.shared.u64 t, %1; cvt.u32.u64 %0, t; }" : "=r"(a) : "l"(p));
    return a;
}
__device__ __forceinline__ void cp_async16(uint32_t dst, const void* src) {
    asm volatile("cp.async.cg.shared.global [%0], [%1], 16;" :: "r"(dst), "l"(src));
}

// Detect int64 vs int32 index buffers
__global__ void detect_i64(const int* __restrict__ w, long n_words, int* flag) {
    long i = (long)blockIdx.x * blockDim.x + threadIdx.x;
    long idx = 2 * i + 1;
    if (idx < n_words && w[idx] != 0) *flag = 0;
}
__device__ __forceinline__ long ld_idx(const void* p, long i, int f64) {
    return f64 ? (long)((const long long*)p)[i] : (long)((const int*)p)[i];
}

// ---------------------------------------------------------------------------
// CSR build (graph is layer-invariant: build once per call)
__global__ void hist_dst(const void* __restrict__ ei, int E,
                         const int* __restrict__ flag, int* __restrict__ deg) {
    int f64 = flag[0];
    int e = blockIdx.x * blockDim.x + threadIdx.x;
    if (e >= E) return;
    int dst = (int)ld_idx(ei, (long)E + e, f64);
    atomicAdd(&deg[dst], 1);
}

__global__ void chunk_sums(const int* __restrict__ deg, int* __restrict__ sums, int N) {
    __shared__ int ws[8];
    int base = blockIdx.x << 10;
    int tid = threadIdx.x;            // 256
    int v = 0;
#pragma unroll
    for (int i = 0; i < 4; i++) {
        int idx = base + tid + i * 256;
        v += (idx < N) ? deg[idx] : 0;
    }
#pragma unroll
    for (int o = 16; o; o >>= 1) v += __shfl_xor_sync(~0u, v, o);
    if ((tid & 31) == 0) ws[tid >> 5] = v;
    __syncthreads();
    if (tid == 0) {
        int s = 0;
#pragma unroll
        for (int i = 0; i < 8; i++) s += ws[i];
        sums[blockIdx.x] = s;
    }
}

__global__ void scan_sums(int* __restrict__ sums, int* __restrict__ rowptr,
                          int nchunks, int N, int E) {
    int lane = threadIdx.x;
    int v0 = (lane < nchunks) ? sums[lane] : 0;
    int v1 = (lane + 32 < nchunks) ? sums[lane + 32] : 0;
    int x0 = v0;
#pragma unroll
    for (int o = 1; o < 32; o <<= 1) {
        int t = __shfl_up_sync(~0u, x0, o);
        if (lane >= o) x0 += t;
    }
    int tot0 = __shfl_sync(~0u, x0, 31);
    int x1 = v1;
#pragma unroll
    for (int o = 1; o < 32; o <<= 1) {
        int t = __shfl_up_sync(~0u, x1, o);
        if (lane >= o) x1 += t;
    }
    x1 += tot0;
    if (lane < nchunks) sums[lane] = x0 - v0;
    if (lane + 32 < nchunks) sums[lane + 32] = x1 - v1;
    if (lane == 0) rowptr[N] = E;
}

__global__ void scan_chunks(const int* __restrict__ deg, const int* __restrict__ csums,
                            int* __restrict__ rowptr, int* __restrict__ cursor, int N) {
    __shared__ int wsum[32];
    int base = blockIdx.x << 10;
    int tid = threadIdx.x, lane = tid & 31, w = tid >> 5;
    int i = base + tid;
    int v = (i < N) ? deg[i] : 0;
    int x = v;
#pragma unroll
    for (int o = 1; o < 32; o <<= 1) {
        int t = __shfl_up_sync(~0u, x, o);
        if (lane >= o) x += t;
    }
    if (lane == 31) wsum[w] = x;
    __syncthreads();
    if (w == 0) {
        int s = wsum[lane];
#pragma unroll
        for (int o = 1; o < 32; o <<= 1) {
            int t = __shfl_up_sync(~0u, s, o);
            if (lane >= o) s += t;
        }
        wsum[lane] = s;
    }
    __syncthreads();
    int excl = x - v + (w ? wsum[w - 1] : 0) + csums[blockIdx.x];
    if (i < N) { rowptr[i] = excl; cursor[i] = excl; }
}

__global__ void fill_csr(const void* __restrict__ ei, int E,
                         const int* __restrict__ flag,
                         int* __restrict__ cursor, int* __restrict__ col) {
    int f64 = flag[0];
    int e = blockIdx.x * blockDim.x + threadIdx.x;
    if (e >= E) return;
    int src = (int)ld_idx(ei, e, f64);
    int dst = (int)ld_idx(ei, (long)E + e, f64);
    int pos = atomicAdd(&cursor[dst], 1);
    col[pos] = src;
}

// ---------------------------------------------------------------------------
// agg[n] = fp16(sum_{j in row n} h[col[j]])  — fp32 accumulation
__global__ void gather_sum(const __half* __restrict__ h, const int* __restrict__ rowptr,
                           const int* __restrict__ col, __half* __restrict__ agg, int N) {
    int n = blockIdx.x;
    if (n >= N) return;
    int lane = threadIdx.x;                      // 128 threads, 4 halves each
    int beg = rowptr[n], end = rowptr[n + 1];
    float4 a0 = make_float4(0.f, 0.f, 0.f, 0.f);
    float4 a1 = make_float4(0.f, 0.f, 0.f, 0.f);
    int j = beg;
    for (; j + 2 <= end; j += 2) {
        int s0 = __ldg(col + j);
        int s1 = __ldg(col + j + 1);
        uint2 v0 = ((const uint2*)(h + (size_t)s0 * H))[lane];
        uint2 v1 = ((const uint2*)(h + (size_t)s1 * H))[lane];
        float2 p0 = __half22float2(*(__half2*)&v0.x);
        float2 p1 = __half22float2(*(__half2*)&v0.y);
        float2 q0 = __half22float2(*(__half2*)&v1.x);
        float2 q1 = __half22float2(*(__half2*)&v1.y);
        a0.x += p0.x; a0.y += p0.y; a0.z += p1.x; a0.w += p1.y;
        a1.x += q0.x; a1.y += q0.y; a1.z += q1.x; a1.w += q1.y;
    }
    if (j < end) {
        int s0 = __ldg(col + j);
        uint2 v0 = ((const uint2*)(h + (size_t)s0 * H))[lane];
        float2 p0 = __half22float2(*(__half2*)&v0.x);
        float2 p1 = __half22float2(*(__half2*)&v0.y);
        a0.x += p0.x; a0.y += p0.y; a0.z += p1.x; a0.w += p1.y;
    }
    a0.x += a1.x; a0.y += a1.y; a0.z += a1.z; a0.w += a1.w;
    __half2 r0 = __floats2half2_rn(a0.x, a0.y);
    __half2 r1 = __floats2half2_rn(a0.z, a0.w);
    uint2 o; o.x = *(uint32_t*)&r0; o.y = *(uint32_t*)&r1;
    ((uint2*)(agg + (size_t)n * H))[lane] = o;
}

// ---------------------------------------------------------------------------
// g_Wt[mat][n][k] = fp16(W[mat][k][n])
__global__ void build_wt(const float* __restrict__ Wr, const float* __restrict__ Wn) {
    int mat = blockIdx.z;
    int l = mat >> 1, s = mat & 1;
    const float* W = (s ? Wn : Wr) + (size_t)l * H * H;
    __half* out = g_Wt + (size_t)mat * H * H;
    __shared__ float t[32][33];
    int kx = blockIdx.x * 32, ny = blockIdx.y * 32;
    int tx = threadIdx.x, ty = threadIdx.y;
#pragma unroll
    for (int j = 0; j < 4; j++)
        t[ty + j * 8][tx] = W[(size_t)(kx + ty + j * 8) * H + ny + tx];
    __syncthreads();
#pragma unroll
    for (int j = 0; j < 4; j++)
        out[(size_t)(ny + ty + j * 8) * H + kx + tx] = __float2half_rn(t[tx][ty + j * 8]);
}

// ---------------------------------------------------------------------------
// h0 = fp16(x @ W_in + b_in)
__global__ void in_gemm(const float* __restrict__ x, const float* __restrict__ Win,
                        const float* __restrict__ bin, __half* __restrict__ h, int N) {
    __shared__ float xs[16][17];
    int nb = blockIdx.x * 16;
    int tid = threadIdx.x;
    {
        int n = tid >> 4, k = tid & 15;
        int gn = nb + n;
        xs[n][k] = (gn < N) ? x[(size_t)gn * INF + k] : 0.f;
    }
    __syncthreads();
    float w0[16], w1[16];
#pragma unroll
    for (int k = 0; k < 16; k++) {
        w0[k] = Win[k * H + tid];
        w1[k] = Win[k * H + tid + 256];
    }
    float b0 = bin[tid], b1 = bin[tid + 256];
    for (int n = 0; n < 16; n++) {
        int gn = nb + n;
        if (gn >= N) break;
        float a0 = b0, a1 = b1;
#pragma unroll
        for (int k = 0; k < 16; k++) {
            float xv = xs[n][k];
            a0 += xv * w0[k];
            a1 += xv * w1[k];
        }
        h[(size_t)gn * H + tid]       = __float2half_rn(a0);
        h[(size_t)gn * H + tid + 256] = __float2half_rn(a1);
    }
}

// ---------------------------------------------------------------------------
// C = fp16(A1@W1' + A2@W2' + bias) via fp16 mma.sync m16n8k16
//   BM=128, BN=128, BK=32 halves, 8 warps (4x2), warp tile 32x64
//   SMEM tiles: 128 rows x 20 words (32 halves data + pad), 80B rows
#define BM 128
#define BN 128
#define BKT 32                                   // halves per K-tile
#define RSW 20                                   // words per row
#define TILE_WORDS (BM * RSW)                    // 2560 words = 10240 B
#define STAGES 3
#define CONV_SMEM (STAGES * 2 * TILE_WORDS * 4)  // 61440 B

__global__ __launch_bounds__(256, 2)
void conv_mma(const __half* __restrict__ A1, const __half* __restrict__ A2,
              const __half* __restrict__ Wt, const float* __restrict__ bias,
              __half* __restrict__ C, int M) {
    extern __shared__ uint32_t smw[];
    uint32_t* Asw = smw;                          // STAGES * TILE_WORDS
    uint32_t* Bsw = smw + STAGES * TILE_WORDS;
    uint32_t aAddr = smem_u32(Asw);
    uint32_t bAddr = smem_u32(Bsw);

    int tid = threadIdx.x;
    int wid = tid >> 5, lane = tid & 31;
    int g = lane >> 2, tig = lane & 3;
    int wm0 = (wid & 3) * 32;
    int wn0 = (wid >> 2) * 64;
    int m0 = blockIdx.x * BM;
    int n0 = blockIdx.y * BN;

    int cprow = tid >> 1;                         // 0..127
    int cpoff = (tid & 1) * 16;                   // halves offset: 0 or 16

    float acc[2][8][4];
#pragma unroll
    for (int i = 0; i < 2; i++)
#pragma unroll
        for (int j = 0; j < 8; j++)
#pragma unroll
            for (int q = 0; q < 4; q++) acc[i][j][q] = 0.f;

    const int NT = 32;                            // 2 sources * 16 K-tiles

    auto issue = [&](int t) {
        int st = t % STAGES;
        int s = t >> 4;
        int kt = (t & 15) * BKT;
        const __half* A = s ? A2 : A1;            // rows < NMAX always valid
        const __half* B = Wt + (size_t)s * H * H;
        uint32_t ab = aAddr + st * (TILE_WORDS * 4);
        uint32_t bb = bAddr + st * (TILE_WORDS * 4);
        uint32_t so = cprow * 80 + cpoff * 2;     // byte offset in tile
        const __half* ag = A + (size_t)(m0 + cprow) * H + kt + cpoff;
        const __half* bg = B + (size_t)(n0 + cprow) * H + kt + cpoff;
        cp_async16(ab + so,      ag);
        cp_async16(ab + so + 16, ag + 8);
        cp_async16(bb + so,      bg);
        cp_async16(bb + so + 16, bg + 8);
        asm volatile("cp.async.commit_group;" ::: "memory");
    };

    issue(0);
    issue(1);

    for (int t = 0; t < NT; t++) {
        if (t + 1 < NT) {
            asm volatile("cp.async.wait_group 1;" ::: "memory");
        } else {
            asm volatile("cp.async.wait_group 0;" ::: "memory");
        }
        __syncthreads();
        if (t + 2 < NT) issue(t + 2);

        const uint32_t* Asb = Asw + (t % STAGES) * TILE_WORDS;
        const uint32_t* Bsb = Bsw + (t % STAGES) * TILE_WORDS;
#pragma unroll
        for (int ks = 0; ks < 2; ks++) {
            int kw = ks * 8;                      // word offset of this k16 step
            uint32_t a[2][4], b[8][2];
#pragma unroll
            for (int i = 0; i < 2; i++) {
                int rb = wm0 + i * 16;
                a[i][0] = Asb[(rb + g) * RSW + kw + tig];
                a[i][1] = Asb[(rb + g + 8) * RSW + kw + tig];
                a[i][2] = Asb[(rb + g) * RSW + kw + tig + 4];
                a[i][3] = Asb[(rb + g + 8) * RSW + kw + tig + 4];
            }
#pragma unroll
            for (int j = 0; j < 8; j++) {
                int nb = wn0 + j * 8;
                b[j][0] = Bsb[(nb + g) * RSW + kw + tig];
                b[j][1] = Bsb[(nb + g) * RSW + kw + tig + 4];
            }
#pragma unroll
            for (int i = 0; i < 2; i++)
#pragma unroll
                for (int j = 0; j < 8; j++)
                    mma_f16(acc[i][j], a[i], b[j]);
        }
    }

    // epilogue: add bias (fp32), store half2 pairs
#pragma unroll
    for (int i = 0; i < 2; i++) {
        int row0 = m0 + wm0 + i * 16 + g;
        int row1 = row0 + 8;
#pragma unroll
        for (int j = 0; j < 8; j++) {
            int col = n0 + wn0 + j * 8 + tig * 2;
            float bx = bias[col], by = bias[col + 1];
            if (row0 < M) {
                __half2 o = __floats2half2_rn(acc[i][j][0] + bx, acc[i][j][1] + by);
                *(__half2*)(C + (size_t)row0 * H + col) = o;
            }
            if (row1 < M) {
                __half2 o = __floats2half2_rn(acc[i][j][2] + bx, acc[i][j][3] + by);
                *(__half2*)(C + (size_t)row1 * H + col) = o;
            }
        }
    }
}

// ---------------------------------------------------------------------------
// In-place LayerNorm + ReLU per row (fp16 storage, fp32 math)
__global__ void ln_relu(__half* __restrict__ h, const float* __restrict__ gamma,
                        const float* __restrict__ beta, int N) {
    long row = blockIdx.x;
    if (row >= N) return;
    int tid = threadIdx.x;                        // 128 threads x 4 halves
    uint2 u = ((const uint2*)(h + row * H))[tid];
    float2 p0 = __half22float2(*(__half2*)&u.x);
    float2 p1 = __half22float2(*(__half2*)&u.y);
    float s  = p0.x + p0.y + p1.x + p1.y;
    float sq = p0.x * p0.x + p0.y * p0.y + p1.x * p1.x + p1.y * p1.y;
#pragma unroll
    for (int o = 16; o; o >>= 1) {
        s  += __shfl_xor_sync(~0u, s, o);
        sq += __shfl_xor_sync(~0u, sq, o);
    }
    __shared__ float ss[4], sqs[4];
    int w = tid >> 5;
    if ((tid & 31) == 0) { ss[w] = s; sqs[w] = sq; }
    __syncthreads();
    s  = ss[0] + ss[1] + ss[2] + ss[3];
    sq = sqs[0] + sqs[1] + sqs[2] + sqs[3];
    float mean = s * (1.f / H);
    float var  = sq * (1.f / H) - mean * mean;
    float rstd = rsqrtf(var + 1e-5f);
    int c = tid * 4;
    float4 gm = *(const float4*)(gamma + c);
    float4 bt = *(const float4*)(beta + c);
    float r0 = fmaxf((p0.x - mean) * rstd * gm.x + bt.x, 0.f);
    float r1 = fmaxf((p0.y - mean) * rstd * gm.y + bt.y, 0.f);
    float r2 = fmaxf((p1.x - mean) * rstd * gm.z + bt.z, 0.f);
    float r3 = fmaxf((p1.y - mean) * rstd * gm.w + bt.w, 0.f);
    __half2 o0 = __floats2half2_rn(r0, r1);
    __half2 o1 = __floats2half2_rn(r2, r3);
    uint2 o; o.x = *(uint32_t*)&o0; o.y = *(uint32_t*)&o1;
    ((uint2*)(h + row * H))[tid] = o;
}

// ---------------------------------------------------------------------------
__global__ void pool(const __half* __restrict__ h, const void* __restrict__ batch,
                     int N, const int* __restrict__ flag) {
    long n = blockIdx.x;
    if (n >= N) return;
    int f64 = flag[0];
    long g = ld_idx(batch, n, f64);
    int lane = threadIdx.x;                       // 128 threads x 4 halves
    uint2 u = ((const uint2*)(h + n * H))[lane];
    float2 p0 = __half22float2(*(__half2*)&u.x);
    float2 p1 = __half22float2(*(__half2*)&u.y);
    red_add_v4(g_pooled + g * H + 4 * lane, make_float4(p0.x, p0.y, p1.x, p1.y));
    if (lane == 0) atomicAdd(&g_counts[g], 1.f);
}

__global__ void out_gemm(const float* __restrict__ Wout, const float* __restrict__ bout,
                         float* __restrict__ out) {
    int g = blockIdx.x;
    __shared__ float ps[H];
    int tid = threadIdx.x;
    float inv = 1.f / fmaxf(g_counts[g], 1.f);
#pragma unroll
    for (int i = 0; i < 4; i++)
        ps[tid + i * 128] = g_pooled[(size_t)g * H + tid + i * 128] * inv;
    __syncthreads();
    float acc[4];
#pragma unroll
    for (int j = 0; j < 4; j++) acc[j] = bout[tid + j * 128];
    for (int k = 0; k < H; k++) {
        float p = ps[k];
#pragma unroll
        for (int j = 0; j < 4; j++)
            acc[j] += p * Wout[(size_t)k * H + tid + j * 128];
    }
#pragma unroll
    for (int j = 0; j < 4; j++) out[(size_t)g * H + tid + j * 128] = acc[j];
}

// ---------------------------------------------------------------------------
extern "C" void kernel_launch(void* const* d_in, const int* in_sizes, int n_in,
                              void* d_out, int out_size) {
    const float* x      = (const float*)d_in[0];
    const void*  ei     = d_in[1];
    const void*  batch  = d_in[2];
    const float* W_in   = (const float*)d_in[3];
    const float* b_in   = (const float*)d_in[4];
    const float* W_root = (const float*)d_in[5];
    const float* W_neigh= (const float*)d_in[6];
    const float* b_conv = (const float*)d_in[7];
    const float* ln_g   = (const float*)d_in[8];
    const float* ln_b   = (const float*)d_in[9];
    const float* W_out  = (const float*)d_in[10];
    const float* b_out  = (const float*)d_in[11];
    float* out = (float*)d_out;

    int N = in_sizes[0] / INF;
    int E = in_sizes[1] / 2;
    int G = out_size / H;
    int nchunks = (N + 1023) / 1024;

    void *pA, *pB, *pAgg, *pWt, *pPool, *pCnt, *pFlags;
    void *pDeg, *pRow, *pCur, *pCsums, *pCol;
    cudaGetSymbolAddress(&pA, g_hA);
    cudaGetSymbolAddress(&pB, g_hB);
    cudaGetSymbolAddress(&pAgg, g_agg);
    cudaGetSymbolAddress(&pWt, g_Wt);
    cudaGetSymbolAddress(&pPool, g_pooled);
    cudaGetSymbolAddress(&pCnt, g_counts);
    cudaGetSymbolAddress(&pFlags, g_flags);
    cudaGetSymbolAddress(&pDeg, g_deg);
    cudaGetSymbolAddress(&pRow, g_rowptr);
    cudaGetSymbolAddress(&pCur, g_cursor);
    cudaGetSymbolAddress(&pCsums, g_csums);
    cudaGetSymbolAddress(&pCol, g_col);
    __half* hA = (__half*)pA;
    __half* hB = (__half*)pB;
    int* flags = (int*)pFlags;

    cudaFuncSetAttribute(conv_mma, cudaFuncAttributeMaxDynamicSharedMemorySize, CONV_SMEM);

    cudaMemsetAsync(pFlags, 1, 2 * sizeof(int));
    {
        long nw = in_sizes[1];
        int blocks = (int)((nw / 2 + 255) / 256);
        detect_i64<<<blocks, 256>>>((const int*)ei, nw, flags + 0);
        nw = in_sizes[2];
        blocks = (int)((nw / 2 + 255) / 256);
        detect_i64<<<blocks, 256>>>((const int*)batch, nw, flags + 1);
    }

    // CSR build (once per call; graph identical across layers)
    cudaMemsetAsync(pDeg, 0, (size_t)N * sizeof(int));
    hist_dst<<<(E + 255) / 256, 256>>>(ei, E, flags, (int*)pDeg);
    chunk_sums<<<nchunks, 256>>>((const int*)pDeg, (int*)pCsums, N);
    scan_sums<<<1, 32>>>((int*)pCsums, (int*)pRow, nchunks, N, E);
    scan_chunks<<<nchunks, 1024>>>((const int*)pDeg, (const int*)pCsums,
                                   (int*)pRow, (int*)pCur, N);
    fill_csr<<<(E + 255) / 256, 256>>>(ei, E, flags, (int*)pCur, (int*)pCol);

    {
        dim3 g2(16, 16, 6);
        build_wt<<<g2, dim3(32, 8)>>>(W_root, W_neigh);
    }
    in_gemm<<<(N + 15) / 16, 256>>>(x, W_in, b_in, hA, N);

    __half* cur = hA;
    __half* nxt = hB;
    for (int l = 0; l < LAYERS; l++) {
        gather_sum<<<N, 128>>>(cur, (const int*)pRow, (const int*)pCol,
                               (__half*)pAgg, N);
        dim3 grid((N + BM - 1) / BM, H / BN);
        conv_mma<<<grid, 256, CONV_SMEM>>>(cur, (const __half*)pAgg,
                                           (const __half*)pWt + (size_t)l * 2 * H * H,
                                           b_conv + (size_t)l * H, nxt, N);
        ln_relu<<<N, 128>>>(nxt, ln_g + (size_t)l * H, ln_b + (size_t)l * H, N);
        __half* t = cur; cur = nxt; nxt = t;
    }

    cudaMemsetAsync(pPool, 0, (size_t)G * H * sizeof(float));
    cudaMemsetAsync(pCnt, 0, G * sizeof(float));
    pool<<<N, 128>>>(cur, batch, N, flags + 1);
    out_gemm<<<G, 128>>>(W_out, b_out, out);
}